// round 7
// baseline (speedup 1.0000x reference)
#include <cuda_runtime.h>
#include <cstdint>

#define NB   16
#define C    64
#define HWSZ 9216
#define CHW  589824
#define KK   576
#define NSLICE 8

// Scratch (static device arrays). Feature maps NHWC: [b][px][c].
__device__ float g_kf[NB * CHW];
__device__ float g_qf[NB * CHW];
__device__ float g_vf[NB * CHW];
__device__ float g_sc[NSLICE][NB * C * KK];
__device__ float g_w9s[3 * 9 * 64 * 64];   // [z][k9][cout][cin], tf32-rounded
__device__ float g_w9d[NB * 9 * 64 * 64];  // [b][k9][cout][cin], tf32-rounded

// tcgen05 is arch-SPECIFIC: only emit in the sm_103a/sm_100a pass.
#if defined(__CUDA_ARCH_FEAT_SM103_ALL) || defined(__CUDA_ARCH_FEAT_SM100_ALL) \
    || (defined(__CUDA_ARCH_SPECIFIC__) && (__CUDA_ARCH_SPECIFIC__ >= 1000))
#define HAS_TCGEN05 1
#else
#define HAS_TCGEN05 0
#endif

__device__ __forceinline__ float tf32r(float x) {
    uint32_t u;
    asm("cvt.rna.tf32.f32 %0, %1;" : "=r"(u) : "f"(x));
    return __uint_as_float(u);
}

#if HAS_TCGEN05
__device__ __forceinline__ uint32_t smem_u32(const void* p) {
    uint32_t a;
    asm("{ .reg .u64 t; cvta.to.shared.u64 t, %1; cvt.u32.u64 %0, t; }"
        : "=r"(a) : "l"(p));
    return a;
}
__device__ __forceinline__ uint32_t elect_one() {
    uint32_t pred;
    asm volatile("{\n\t.reg .pred p;\n\telect.sync _|p, 0xFFFFFFFF;\n\t"
                 "selp.b32 %0, 1, 0, p;\n\t}" : "=r"(pred));
    return pred;
}

#define MBARRIER_INIT(addr, cnt) \
    asm volatile("mbarrier.init.shared.b64 [%0], %1;" :: "r"(addr), "r"(cnt) : "memory")
#define MBARRIER_INVAL(addr) \
    asm volatile("mbarrier.inval.shared.b64 [%0];" :: "r"(addr) : "memory")
#define MBARRIER_WAIT_PARITY(addr, par) do {                                   \
    uint32_t _m = (addr), _p = (par), _d;                                      \
    asm volatile("{\n\t.reg .pred p;\n\t"                                      \
        "mbarrier.try_wait.parity.acquire.cta.shared::cta.b64 p, [%1], %2;\n\t"\
        "selp.b32 %0, 1, 0, p;\n\t}" : "=r"(_d) : "r"(_m), "r"(_p) : "memory");\
    if (!_d) {                                                                 \
        asm volatile("{\n\t.reg .pred P1;\n\tWL%=:\n\t"                        \
        "mbarrier.try_wait.parity.acquire.cta.shared::cta.b64 P1, [%0], %1, 0x989680;\n\t" \
        "@P1 bra.uni WD%=;\n\tbra.uni WL%=;\n\tWD%=:\n\t}"                     \
        :: "r"(_m), "r"(_p) : "memory");                                       \
    } } while (0)

#define TCGEN05_ALLOC(res, n) \
    asm volatile("tcgen05.alloc.cta_group::1.sync.aligned.shared::cta.b32 [%0], %1;" \
                 :: "r"(res), "r"((uint32_t)(n)) : "memory")
#define TCGEN05_DEALLOC(t, n) \
    asm volatile("tcgen05.dealloc.cta_group::1.sync.aligned.b32 %0, %1;" :: "r"(t), "r"((uint32_t)(n)))
#define TCGEN05_RELINQ() \
    asm volatile("tcgen05.relinquish_alloc_permit.cta_group::1.sync.aligned;")
#define TCGEN05_COMMIT(mb) \
    asm volatile("tcgen05.commit.cta_group::1.mbarrier::arrive::one.shared::cluster.b64 [%0];" \
                 :: "r"(mb) : "memory")
#define TCGEN05_FENCE_AFTER()  asm volatile("tcgen05.fence::after_thread_sync;" ::: "memory")
#define TCGEN05_FENCE_BEFORE() asm volatile("tcgen05.fence::before_thread_sync;" ::: "memory")
#define TCGEN05_WAIT_LD()      asm volatile("tcgen05.wait::ld.sync.aligned;" ::: "memory")
#define FENCE_ASYNC_SHARED()   asm volatile("fence.proxy.async.shared::cta;" ::: "memory")

#define TCGEN05_LD_X32(r, ta) \
    asm volatile("tcgen05.ld.sync.aligned.32x32b.x32.b32 "                     \
        "{%0,%1,%2,%3,%4,%5,%6,%7,%8,%9,%10,%11,%12,%13,%14,%15,"             \
        "%16,%17,%18,%19,%20,%21,%22,%23,%24,%25,%26,%27,%28,%29,%30,%31}, [%32];" \
        : "=r"((r)[0]),"=r"((r)[1]),"=r"((r)[2]),"=r"((r)[3]),                 \
          "=r"((r)[4]),"=r"((r)[5]),"=r"((r)[6]),"=r"((r)[7]),                 \
          "=r"((r)[8]),"=r"((r)[9]),"=r"((r)[10]),"=r"((r)[11]),               \
          "=r"((r)[12]),"=r"((r)[13]),"=r"((r)[14]),"=r"((r)[15]),             \
          "=r"((r)[16]),"=r"((r)[17]),"=r"((r)[18]),"=r"((r)[19]),             \
          "=r"((r)[20]),"=r"((r)[21]),"=r"((r)[22]),"=r"((r)[23]),             \
          "=r"((r)[24]),"=r"((r)[25]),"=r"((r)[26]),"=r"((r)[27]),             \
          "=r"((r)[28]),"=r"((r)[29]),"=r"((r)[30]),"=r"((r)[31])              \
        : "r"(ta))

__device__ __forceinline__ void mma_tf32(uint32_t d, uint64_t a, uint64_t b,
                                         uint32_t idesc, uint32_t en) {
    asm volatile("{\n\t.reg .pred p;\n\tsetp.ne.u32 p, %5, 0;\n\t"
                 "tcgen05.mma.cta_group::1.kind::tf32 [%0], %1, %2, %3, {%4,%4,%4,%4}, p;\n\t}"
                 :: "r"(d), "l"(a), "l"(b), "r"(idesc), "r"(0u), "r"(en) : "memory");
}

static __device__ __forceinline__ uint64_t mk_desc(uint32_t addr) {
    return ((uint64_t)2 << 61) | ((uint64_t)1 << 46) | ((uint64_t)64 << 32)
         | ((uint64_t)1 << 16) | (uint64_t)((addr >> 4) & 0x3FFF);
}
__device__ __forceinline__ uint32_t sw128(uint32_t off) { return off ^ ((off >> 3) & 0x70); }

// idesc: D=F32, a=TF32, b=TF32, K-major both, N=64, M=128
#define IDESC_TF32 ((1u<<4) | (2u<<7) | (2u<<10) | ((64u/8u)<<17) | ((128u/16u)<<24))
#endif  // HAS_TCGEN05

#define NBUF       6
#define ABUF_BYTES 16384              // 128 rows * 128B
#define BREG_OFF   (NBUF * ABUF_BYTES)
#define SMEM_DYN   (1024 + BREG_OFF + 9 * 8192)

// ---------------------------------------------------------------------------
// Tensor-core conv. Grid (12, 16, z). 256 threads.
// ---------------------------------------------------------------------------
__global__ void __launch_bounds__(256, 1)
conv_tc_kernel(const float* __restrict__ x1, const float* __restrict__ x2,
               float* __restrict__ out, int dyn)
{
#if HAS_TCGEN05
    extern __shared__ char smem[];
    __shared__ uint32_t s_tmem;
    __shared__ alignas(16) unsigned long long s_mbar[4];

    const int tid = threadIdx.x;
    const int wid = tid >> 5, lid = tid & 31;
    const int r0  = blockIdx.x * 8;
    const int b   = blockIdx.y;
    const int z   = blockIdx.z;

    uint32_t sm0 = smem_u32(smem);
    uint32_t Ab  = (sm0 + 1023) & ~1023u;
    uint32_t Bb  = Ab + BREG_OFF;
    char* Abp = smem + (Ab - sm0);
    char* Bbp = smem + (Bb - sm0);
    uint32_t mb[4] = { smem_u32(&s_mbar[0]), smem_u32(&s_mbar[1]),
                       smem_u32(&s_mbar[2]), smem_u32(&s_mbar[3]) };

    if (wid == 0) TCGEN05_ALLOC(smem_u32(&s_tmem), 512);
    if (tid < 4) MBARRIER_INIT(mb[tid], 1);
    // zero constant halo rows (row 0 = col -1; rows 97..127) of all buffers
    for (int i = tid; i < NBUF * 32 * 32; i += 256) {
        int buf = i >> 10, rr = i & 1023, row = rr >> 5, wd = rr & 31;
        int prow = (row == 0) ? 0 : (96 + row);
        *(float*)(Abp + buf * ABUF_BYTES + prow * 128 + wd * 4) = 0.f;
    }
    if (wid == 0) TCGEN05_RELINQ();
    __syncthreads();
    const uint32_t tmem = s_tmem;

    const float* xsrc = dyn ? nullptr : ((z == 1) ? x2 : x1);

    int ncommit = 0;
    for (int h = 0; h < 2; h++) {
        if (ncommit > 0) {       // B tile reused: drain all prior MMAs
            int k = ncommit - 1;
            MBARRIER_WAIT_PARITY(mb[k & 3], (k >> 2) & 1);
        }
        // ---- load B: 9 shifts x 64 cout x 32 cin ----
        #pragma unroll 4
        for (int it = 0; it < 18; it++) {
            int idx = it * 256 + tid;
            int k9 = idx >> 9, r2 = idx & 511, co = r2 >> 3, ci4 = r2 & 7;
            const float* src = dyn
                ? &g_w9d[(((size_t)b * 9 + k9) * 64 + co) * 64 + h * 32 + ci4 * 4]
                : &g_w9s[(((size_t)z * 9 + k9) * 64 + co) * 64 + h * 32 + ci4 * 4];
            float4 v = *(const float4*)src;
            *(float4*)(Bbp + k9 * 8192 + sw128(co * 128 + ci4 * 16)) = v;
        }
        // ---- A loader: one image row -> one buffer (256 threads) ----
        auto load_a = [&](char* abuf, int ri) {
            bool valid = (ri >= 0) && (ri < 96);
            if (!dyn) {
                const float* src = xsrc + (size_t)b * CHW;
                #pragma unroll
                for (int it = 0; it < 3; it++) {
                    int idx = it * 256 + tid;
                    int cin = idx / 24, c4 = idx % 24;
                    float4 v = make_float4(0.f, 0.f, 0.f, 0.f);
                    if (valid)
                        v = *(const float4*)(src + (size_t)(h * 32 + cin) * HWSZ
                                             + ri * 96 + c4 * 4);
                    float vv[4] = {v.x, v.y, v.z, v.w};
                    #pragma unroll
                    for (int j = 0; j < 4; j++)
                        *(float*)(abuf + sw128((c4 * 4 + j + 1) * 128 + cin * 4))
                            = tf32r(vv[j]);
                }
            } else {
                const float* src = g_vf + (size_t)b * CHW;
                #pragma unroll
                for (int it = 0; it < 3; it++) {
                    int idx = it * 256 + tid;
                    int col = idx >> 3, ci4 = idx & 7;
                    float4 v = make_float4(0.f, 0.f, 0.f, 0.f);
                    if (valid)
                        v = *(const float4*)(src + (size_t)(ri * 96 + col) * 64
                                             + h * 32 + ci4 * 4);
                    float4 w4 = make_float4(tf32r(v.x), tf32r(v.y), tf32r(v.z), tf32r(v.w));
                    *(float4*)(abuf + sw128((col + 1) * 128 + ci4 * 16)) = w4;
                }
            }
        };
        // prologue: buffers 0,1,2 = image rows r0-1, r0, r0+1
        for (int i = 0; i < 3; i++) load_a(Abp + i * ABUF_BYTES, r0 - 1 + i);
        __syncthreads();
        FENCE_ASYNC_SHARED();

        for (int r = 0; r < 8; r++) {
            if (wid == 0 && elect_one()) {
                #pragma unroll
                for (int s = 0; s < 9; s++) {
                    int kh = s / 3, kw = s - kh * 3;
                    int buf = (r + kh) % NBUF;
                    uint64_t ad = mk_desc(Ab + buf * ABUF_BYTES + kw * 128);
                    uint64_t bd = mk_desc(Bb + s * 8192);
                    #pragma unroll
                    for (int ks = 0; ks < 4; ks++)
                        mma_tf32(tmem + r * 64, ad + ks * 2, bd + ks * 2,
                                 IDESC_TF32, (h | s | ks) != 0);
                }
                TCGEN05_COMMIT(mb[ncommit & 3]);
            }
            ncommit++;
            if (r < 7) {
                // buffer (r+3)%NBUF last read by pass r-3 -> wait it (3 deep)
                if (r >= 3) {
                    int k = ncommit - 4;
                    MBARRIER_WAIT_PARITY(mb[k & 3], (k >> 2) & 1);
                }
                load_a(Abp + ((r + 3) % NBUF) * ABUF_BYTES, r0 + r + 2);
                __syncthreads();
                FENCE_ASYNC_SHARED();
            }
        }
    }
    { int k = ncommit - 1; MBARRIER_WAIT_PARITY(mb[k & 3], (k >> 2) & 1); }
    TCGEN05_FENCE_AFTER();

    // ---- epilogue: 6 warps; warps 0-2 cols 0..31, warps 4-6 cols 32..63 ----
    if ((wid & 3) < 3) {
        int half = wid >> 2;            // 0 or 1
        int px   = (wid & 3) * 32 + lid;
        for (int r = 0; r < 8; r++) {
            uint32_t d0[32];
            TCGEN05_LD_X32(d0, tmem + r * 64 + half * 32);
            TCGEN05_WAIT_LD();
            if (!dyn) {
                float* dst = ((z == 0) ? g_kf : (z == 1) ? g_qf : g_vf)
                           + ((size_t)b * HWSZ + (size_t)(r0 + r) * 96 + px) * 64
                           + half * 32;
                #pragma unroll
                for (int q = 0; q < 8; q++)
                    *(float4*)(dst + q * 4) = make_float4(
                        __uint_as_float(d0[q*4]),   __uint_as_float(d0[q*4+1]),
                        __uint_as_float(d0[q*4+2]), __uint_as_float(d0[q*4+3]));
            } else {
                float* dst = out + (size_t)b * CHW + (size_t)(r0 + r) * 96 + px
                           + (size_t)half * 32 * HWSZ;
                #pragma unroll
                for (int c = 0; c < 32; c++)
                    dst[(size_t)c * HWSZ] = __uint_as_float(d0[c]);
            }
        }
    }
    TCGEN05_FENCE_BEFORE();
    __syncthreads();
    if (tid < 4) MBARRIER_INVAL(mb[tid]);
    __syncthreads();
    if (wid == 0) TCGEN05_DEALLOC(tmem, 512);
#endif  // HAS_TCGEN05
}

// ---------------------------------------------------------------------------
// Static-weight transpose + tf32 round: w9s[z][k][cout][cin]
// ---------------------------------------------------------------------------
__global__ void __launch_bounds__(256) prep_w9s_kernel(
    const float* __restrict__ w1, const float* __restrict__ w2,
    const float* __restrict__ w3)
{
    int idx = blockIdx.x * 256 + threadIdx.x;
    if (idx >= 3 * 9 * 4096) return;
    int z = idx / 36864, rem = idx - z * 36864;
    int k = rem >> 12, r2 = rem & 4095, co = r2 >> 6, ci = r2 & 63;
    const float* w = (z == 0) ? w1 : (z == 1) ? w2 : w3;
    g_w9s[idx] = tf32r(w[co * 576 + ci * 9 + k]);
}

// ---------------------------------------------------------------------------
// scores partials (NHWC). Grid (9, 16, NSLICE), block 256. 128 L per slice.
// ---------------------------------------------------------------------------
__global__ void __launch_bounds__(256) scores_kernel()
{
    const int k  = blockIdx.x, b = blockIdx.y, s = blockIdx.z;
    const int kh = k / 3, kw = k % 3;
    const float* kfb = g_kf + (size_t)b * CHW;
    const float* qfb = g_qf + (size_t)b * CHW;

    __shared__ float SK[32][68];
    __shared__ float SQ[32][68];

    const int tid = threadIdx.x;
    const int tc  = (tid & 15) << 2;
    const int td  = (tid >> 4) << 2;

    float acc[4][4] = {};
    for (int l0 = s * 128; l0 < s * 128 + 128; l0 += 32) {
        __syncthreads();
        #pragma unroll
        for (int it = 0; it < 8; it++) {
            int idx = tid + it * 256;           // 0..2047
            int li = idx >> 6, c = idx & 63;
            int l = l0 + li;
            int pix = (3 * (l >> 5) + kh) * 96 + 3 * (l & 31) + kw;
            SK[li][c] = kfb[(size_t)pix * 64 + c];
            SQ[li][c] = qfb[(size_t)pix * 64 + c];
        }
        __syncthreads();
        #pragma unroll 8
        for (int li = 0; li < 32; li++) {
            float4 av = *reinterpret_cast<const float4*>(&SK[li][tc]);
            float4 bv = *reinterpret_cast<const float4*>(&SQ[li][td]);
            float a[4]  = {av.x, av.y, av.z, av.w};
            float bb[4] = {bv.x, bv.y, bv.z, bv.w};
            #pragma unroll
            for (int i = 0; i < 4; i++)
                #pragma unroll
                for (int j = 0; j < 4; j++)
                    acc[i][j] = fmaf(a[i], bb[j], acc[i][j]);
        }
    }
    const float sc = 1.0f / 24.0f;
    #pragma unroll
    for (int j = 0; j < 4; j++) {
        float* ap = g_sc[s] + ((size_t)(b * C + td + j)) * KK + k;
        #pragma unroll
        for (int i = 0; i < 4; i++)
            ap[(tc + i) * 9] = acc[i][j] * sc;
    }
}

// ---------------------------------------------------------------------------
// Reduce partials + softmax; write dyn weights w9d[b][k][d][c] (tf32).
// ---------------------------------------------------------------------------
__global__ void __launch_bounds__(256) softmax_kernel()
{
    const int row  = blockIdx.x * 8 + (threadIdx.x >> 5);   // b*64 + d
    const int lane = threadIdx.x & 31;
    const int b = row >> 6, d = row & 63;
    const size_t off = (size_t)row * KK;

    float v[18];
    float m = -3.4e38f;
    #pragma unroll
    for (int i = 0; i < 18; i++) {
        int idx = lane + i * 32;
        float t = 0.f;
        #pragma unroll
        for (int s = 0; s < NSLICE; s++) t += g_sc[s][off + idx];
        v[i] = t;
        m = fmaxf(m, t);
    }
    #pragma unroll
    for (int o = 16; o > 0; o >>= 1) m = fmaxf(m, __shfl_xor_sync(0xffffffffu, m, o));
    float ss = 0.f;
    #pragma unroll
    for (int i = 0; i < 18; i++) { v[i] = __expf(v[i] - m); ss += v[i]; }
    #pragma unroll
    for (int o = 16; o > 0; o >>= 1) ss += __shfl_xor_sync(0xffffffffu, ss, o);
    float inv = 1.0f / ss;
    #pragma unroll
    for (int i = 0; i < 18; i++) {
        int idx = lane + i * 32;           // idx = c*9 + k
        int c = idx / 9, k = idx - c * 9;
        g_w9d[(((size_t)b * 9 + k) * 64 + d) * 64 + c] = tf32r(v[i] * inv);
    }
}

extern "C" void kernel_launch(void* const* d_in, const int* in_sizes, int n_in,
                              void* d_out, int out_size)
{
    const float* x1 = (const float*)d_in[0];
    const float* x2 = (const float*)d_in[1];
    const float* w1 = (const float*)d_in[2];
    const float* w2 = (const float*)d_in[3];
    const float* w3 = (const float*)d_in[4];
    float* out = (float*)d_out;

    cudaFuncSetAttribute(conv_tc_kernel,
                         cudaFuncAttributeMaxDynamicSharedMemorySize, SMEM_DYN);

    prep_w9s_kernel<<<(3 * 9 * 4096 + 255) / 256, 256>>>(w1, w2, w3);
    conv_tc_kernel<<<dim3(12, 16, 3), 256, SMEM_DYN>>>(x1, x2, out, 0);
    scores_kernel<<<dim3(9, 16, NSLICE), 256>>>();
    softmax_kernel<<<128, 256>>>();
    conv_tc_kernel<<<dim3(12, 16, 1), 256, SMEM_DYN>>>(x1, x2, out, 1);
}

// round 8
// speedup vs baseline: 1.0001x; 1.0001x over previous
#include <cuda_runtime.h>
#include <cstdint>

#define NB   16
#define C    64
#define HWSZ 9216
#define CHW  589824
#define KK   576
#define NSLICE 8

// Scratch (static device arrays). Feature maps NHWC: [b][px][c].
__device__ float g_kf[NB * CHW];
__device__ float g_qf[NB * CHW];
__device__ float g_vf[NB * CHW];
__device__ float g_sc[NSLICE][NB * C * KK];
__device__ float g_w9s[3 * 9 * 64 * 64];   // [z][k9][cout][cin], tf32-rounded
__device__ float g_w9d[NB * 9 * 64 * 64];  // [b][k9][cout][cin], tf32-rounded

// tcgen05 is arch-SPECIFIC: only emit in the sm_103a/sm_100a pass.
#if defined(__CUDA_ARCH_FEAT_SM103_ALL) || defined(__CUDA_ARCH_FEAT_SM100_ALL) \
    || (defined(__CUDA_ARCH_SPECIFIC__) && (__CUDA_ARCH_SPECIFIC__ >= 1000))
#define HAS_TCGEN05 1
#else
#define HAS_TCGEN05 0
#endif

__device__ __forceinline__ float tf32r(float x) {
    uint32_t u;
    asm("cvt.rna.tf32.f32 %0, %1;" : "=r"(u) : "f"(x));
    return __uint_as_float(u);
}

#if HAS_TCGEN05
__device__ __forceinline__ uint32_t smem_u32(const void* p) {
    uint32_t a;
    asm("{ .reg .u64 t; cvta.to.shared.u64 t, %1; cvt.u32.u64 %0, t; }"
        : "=r"(a) : "l"(p));
    return a;
}
__device__ __forceinline__ uint32_t elect_one() {
    uint32_t pred;
    asm volatile("{\n\t.reg .pred p;\n\telect.sync _|p, 0xFFFFFFFF;\n\t"
                 "selp.b32 %0, 1, 0, p;\n\t}" : "=r"(pred));
    return pred;
}

#define MBARRIER_INIT(addr, cnt) \
    asm volatile("mbarrier.init.shared.b64 [%0], %1;" :: "r"(addr), "r"(cnt) : "memory")
#define MBARRIER_INVAL(addr) \
    asm volatile("mbarrier.inval.shared.b64 [%0];" :: "r"(addr) : "memory")
#define MBARRIER_WAIT_PARITY(addr, par) do {                                   \
    uint32_t _m = (addr), _p = (par), _d;                                      \
    asm volatile("{\n\t.reg .pred p;\n\t"                                      \
        "mbarrier.try_wait.parity.acquire.cta.shared::cta.b64 p, [%1], %2;\n\t"\
        "selp.b32 %0, 1, 0, p;\n\t}" : "=r"(_d) : "r"(_m), "r"(_p) : "memory");\
    if (!_d) {                                                                 \
        asm volatile("{\n\t.reg .pred P1;\n\tWL%=:\n\t"                        \
        "mbarrier.try_wait.parity.acquire.cta.shared::cta.b64 P1, [%0], %1, 0x989680;\n\t" \
        "@P1 bra.uni WD%=;\n\tbra.uni WL%=;\n\tWD%=:\n\t}"                     \
        :: "r"(_m), "r"(_p) : "memory");                                       \
    } } while (0)

#define TCGEN05_ALLOC(res, n) \
    asm volatile("tcgen05.alloc.cta_group::1.sync.aligned.shared::cta.b32 [%0], %1;" \
                 :: "r"(res), "r"((uint32_t)(n)) : "memory")
#define TCGEN05_DEALLOC(t, n) \
    asm volatile("tcgen05.dealloc.cta_group::1.sync.aligned.b32 %0, %1;" :: "r"(t), "r"((uint32_t)(n)))
#define TCGEN05_RELINQ() \
    asm volatile("tcgen05.relinquish_alloc_permit.cta_group::1.sync.aligned;")
#define TCGEN05_COMMIT(mb) \
    asm volatile("tcgen05.commit.cta_group::1.mbarrier::arrive::one.shared::cluster.b64 [%0];" \
                 :: "r"(mb) : "memory")
#define TCGEN05_FENCE_AFTER()  asm volatile("tcgen05.fence::after_thread_sync;" ::: "memory")
#define TCGEN05_FENCE_BEFORE() asm volatile("tcgen05.fence::before_thread_sync;" ::: "memory")
#define TCGEN05_WAIT_LD()      asm volatile("tcgen05.wait::ld.sync.aligned;" ::: "memory")
#define FENCE_ASYNC_SHARED()   asm volatile("fence.proxy.async.shared::cta;" ::: "memory")

#define TCGEN05_LD_X32(r, ta) \
    asm volatile("tcgen05.ld.sync.aligned.32x32b.x32.b32 "                     \
        "{%0,%1,%2,%3,%4,%5,%6,%7,%8,%9,%10,%11,%12,%13,%14,%15,"             \
        "%16,%17,%18,%19,%20,%21,%22,%23,%24,%25,%26,%27,%28,%29,%30,%31}, [%32];" \
        : "=r"((r)[0]),"=r"((r)[1]),"=r"((r)[2]),"=r"((r)[3]),                 \
          "=r"((r)[4]),"=r"((r)[5]),"=r"((r)[6]),"=r"((r)[7]),                 \
          "=r"((r)[8]),"=r"((r)[9]),"=r"((r)[10]),"=r"((r)[11]),               \
          "=r"((r)[12]),"=r"((r)[13]),"=r"((r)[14]),"=r"((r)[15]),             \
          "=r"((r)[16]),"=r"((r)[17]),"=r"((r)[18]),"=r"((r)[19]),             \
          "=r"((r)[20]),"=r"((r)[21]),"=r"((r)[22]),"=r"((r)[23]),             \
          "=r"((r)[24]),"=r"((r)[25]),"=r"((r)[26]),"=r"((r)[27]),             \
          "=r"((r)[28]),"=r"((r)[29]),"=r"((r)[30]),"=r"((r)[31])              \
        : "r"(ta))

__device__ __forceinline__ void mma_tf32(uint32_t d, uint64_t a, uint64_t b,
                                         uint32_t idesc, uint32_t en) {
    asm volatile("{\n\t.reg .pred p;\n\tsetp.ne.u32 p, %5, 0;\n\t"
                 "tcgen05.mma.cta_group::1.kind::tf32 [%0], %1, %2, %3, {%4,%4,%4,%4}, p;\n\t}"
                 :: "r"(d), "l"(a), "l"(b), "r"(idesc), "r"(0u), "r"(en) : "memory");
}

static __device__ __forceinline__ uint64_t mk_desc(uint32_t addr) {
    return ((uint64_t)2 << 61) | ((uint64_t)1 << 46) | ((uint64_t)64 << 32)
         | ((uint64_t)1 << 16) | (uint64_t)((addr >> 4) & 0x3FFF);
}
__device__ __forceinline__ uint32_t sw128(uint32_t off) { return off ^ ((off >> 3) & 0x70); }

// idesc: D=F32, a=TF32, b=TF32, K-major both, N=64, M=128
#define IDESC_TF32 ((1u<<4) | (2u<<7) | (2u<<10) | ((64u/8u)<<17) | ((128u/16u)<<24))
#endif  // HAS_TCGEN05

#define NBUF       6
#define ABUF_BYTES 16384              // 128 rows * 128B
#define BREG_OFF   (NBUF * ABUF_BYTES)
#define SMEM_DYN   (1024 + BREG_OFF + 9 * 8192)

// ---------------------------------------------------------------------------
// Tensor-core conv. Grid (12, 16, z). 256 threads.
// ---------------------------------------------------------------------------
__global__ void __launch_bounds__(256, 1)
conv_tc_kernel(const float* __restrict__ x1, const float* __restrict__ x2,
               float* __restrict__ out, int dyn)
{
#if HAS_TCGEN05
    extern __shared__ char smem[];
    __shared__ uint32_t s_tmem;
    __shared__ alignas(16) unsigned long long s_mbar[4];

    const int tid = threadIdx.x;
    const int wid = tid >> 5, lid = tid & 31;
    const int r0  = blockIdx.x * 8;
    const int b   = blockIdx.y;
    const int z   = blockIdx.z;

    uint32_t sm0 = smem_u32(smem);
    uint32_t Ab  = (sm0 + 1023) & ~1023u;
    uint32_t Bb  = Ab + BREG_OFF;
    char* Abp = smem + (Ab - sm0);
    char* Bbp = smem + (Bb - sm0);
    uint32_t mb[4] = { smem_u32(&s_mbar[0]), smem_u32(&s_mbar[1]),
                       smem_u32(&s_mbar[2]), smem_u32(&s_mbar[3]) };

    if (wid == 0) TCGEN05_ALLOC(smem_u32(&s_tmem), 512);
    if (tid < 4) MBARRIER_INIT(mb[tid], 1);
    // zero constant halo rows (row 0 = col -1; rows 97..127) of all buffers
    for (int i = tid; i < NBUF * 32 * 32; i += 256) {
        int buf = i >> 10, rr = i & 1023, row = rr >> 5, wd = rr & 31;
        int prow = (row == 0) ? 0 : (96 + row);
        *(float*)(Abp + buf * ABUF_BYTES + prow * 128 + wd * 4) = 0.f;
    }
    if (wid == 0) TCGEN05_RELINQ();
    __syncthreads();
    const uint32_t tmem = s_tmem;

    const float* xsrc = dyn ? nullptr : ((z == 1) ? x2 : x1);

    int ncommit = 0;
    for (int h = 0; h < 2; h++) {
        if (ncommit > 0) {       // B tile reused: drain all prior MMAs
            int k = ncommit - 1;
            MBARRIER_WAIT_PARITY(mb[k & 3], (k >> 2) & 1);
        }
        // ---- load B: 9 shifts x 64 cout x 32 cin ----
        #pragma unroll 4
        for (int it = 0; it < 18; it++) {
            int idx = it * 256 + tid;
            int k9 = idx >> 9, r2 = idx & 511, co = r2 >> 3, ci4 = r2 & 7;
            const float* src = dyn
                ? &g_w9d[(((size_t)b * 9 + k9) * 64 + co) * 64 + h * 32 + ci4 * 4]
                : &g_w9s[(((size_t)z * 9 + k9) * 64 + co) * 64 + h * 32 + ci4 * 4];
            float4 v = *(const float4*)src;
            *(float4*)(Bbp + k9 * 8192 + sw128(co * 128 + ci4 * 16)) = v;
        }
        // ---- A loader: one image row -> one buffer (256 threads) ----
        auto load_a = [&](char* abuf, int ri) {
            bool valid = (ri >= 0) && (ri < 96);
            if (!dyn) {
                const float* src = xsrc + (size_t)b * CHW;
                #pragma unroll
                for (int it = 0; it < 3; it++) {
                    int idx = it * 256 + tid;
                    int cin = idx / 24, c4 = idx % 24;
                    float4 v = make_float4(0.f, 0.f, 0.f, 0.f);
                    if (valid)
                        v = *(const float4*)(src + (size_t)(h * 32 + cin) * HWSZ
                                             + ri * 96 + c4 * 4);
                    float vv[4] = {v.x, v.y, v.z, v.w};
                    #pragma unroll
                    for (int j = 0; j < 4; j++)
                        *(float*)(abuf + sw128((c4 * 4 + j + 1) * 128 + cin * 4))
                            = tf32r(vv[j]);
                }
            } else {
                const float* src = g_vf + (size_t)b * CHW;
                #pragma unroll
                for (int it = 0; it < 3; it++) {
                    int idx = it * 256 + tid;
                    int col = idx >> 3, ci4 = idx & 7;
                    float4 v = make_float4(0.f, 0.f, 0.f, 0.f);
                    if (valid)
                        v = *(const float4*)(src + (size_t)(ri * 96 + col) * 64
                                             + h * 32 + ci4 * 4);
                    float4 w4 = make_float4(tf32r(v.x), tf32r(v.y), tf32r(v.z), tf32r(v.w));
                    *(float4*)(abuf + sw128((col + 1) * 128 + ci4 * 16)) = w4;
                }
            }
        };
        // prologue: buffers 0,1,2 = image rows r0-1, r0, r0+1
        for (int i = 0; i < 3; i++) load_a(Abp + i * ABUF_BYTES, r0 - 1 + i);
        __syncthreads();
        FENCE_ASYNC_SHARED();

        for (int r = 0; r < 8; r++) {
            if (wid == 0 && elect_one()) {
                #pragma unroll
                for (int s = 0; s < 9; s++) {
                    int kh = s / 3, kw = s - kh * 3;
                    int buf = (r + kh) % NBUF;
                    uint64_t ad = mk_desc(Ab + buf * ABUF_BYTES + kw * 128);
                    uint64_t bd = mk_desc(Bb + s * 8192);
                    #pragma unroll
                    for (int ks = 0; ks < 4; ks++)
                        mma_tf32(tmem + r * 64, ad + ks * 2, bd + ks * 2,
                                 IDESC_TF32, (h | s | ks) != 0);
                }
                TCGEN05_COMMIT(mb[ncommit & 3]);
            }
            ncommit++;
            if (r < 7) {
                // buffer (r+3)%NBUF last read by pass r-3 -> wait it (3 deep)
                if (r >= 3) {
                    int k = ncommit - 4;
                    MBARRIER_WAIT_PARITY(mb[k & 3], (k >> 2) & 1);
                }
                load_a(Abp + ((r + 3) % NBUF) * ABUF_BYTES, r0 + r + 2);
                __syncthreads();
                FENCE_ASYNC_SHARED();
            }
        }
    }
    { int k = ncommit - 1; MBARRIER_WAIT_PARITY(mb[k & 3], (k >> 2) & 1); }
    TCGEN05_FENCE_AFTER();

    // ---- epilogue: 6 warps; warps 0-2 cols 0..31, warps 4-6 cols 32..63 ----
    if ((wid & 3) < 3) {
        int half = wid >> 2;            // 0 or 1
        int px   = (wid & 3) * 32 + lid;
        for (int r = 0; r < 8; r++) {
            uint32_t d0[32];
            TCGEN05_LD_X32(d0, tmem + r * 64 + half * 32);
            TCGEN05_WAIT_LD();
            if (!dyn) {
                float* dst = ((z == 0) ? g_kf : (z == 1) ? g_qf : g_vf)
                           + ((size_t)b * HWSZ + (size_t)(r0 + r) * 96 + px) * 64
                           + half * 32;
                #pragma unroll
                for (int q = 0; q < 8; q++)
                    *(float4*)(dst + q * 4) = make_float4(
                        __uint_as_float(d0[q*4]),   __uint_as_float(d0[q*4+1]),
                        __uint_as_float(d0[q*4+2]), __uint_as_float(d0[q*4+3]));
            } else {
                float* dst = out + (size_t)b * CHW + (size_t)(r0 + r) * 96 + px
                           + (size_t)half * 32 * HWSZ;
                #pragma unroll
                for (int c = 0; c < 32; c++)
                    dst[(size_t)c * HWSZ] = __uint_as_float(d0[c]);
            }
        }
    }
    TCGEN05_FENCE_BEFORE();
    __syncthreads();
    if (tid < 4) MBARRIER_INVAL(mb[tid]);
    __syncthreads();
    if (wid == 0) TCGEN05_DEALLOC(tmem, 512);
#endif  // HAS_TCGEN05
}

// ---------------------------------------------------------------------------
// Static-weight transpose + tf32 round: w9s[z][k][cout][cin]
// ---------------------------------------------------------------------------
__global__ void __launch_bounds__(256) prep_w9s_kernel(
    const float* __restrict__ w1, const float* __restrict__ w2,
    const float* __restrict__ w3)
{
    int idx = blockIdx.x * 256 + threadIdx.x;
    if (idx >= 3 * 9 * 4096) return;
    int z = idx / 36864, rem = idx - z * 36864;
    int k = rem >> 12, r2 = rem & 4095, co = r2 >> 6, ci = r2 & 63;
    const float* w = (z == 0) ? w1 : (z == 1) ? w2 : w3;
    g_w9s[idx] = tf32r(w[co * 576 + ci * 9 + k]);
}

// ---------------------------------------------------------------------------
// scores partials (NHWC). Grid (9, 16, NSLICE), block 256. 128 L per slice.
// ---------------------------------------------------------------------------
__global__ void __launch_bounds__(256) scores_kernel()
{
    const int k  = blockIdx.x, b = blockIdx.y, s = blockIdx.z;
    const int kh = k / 3, kw = k % 3;
    const float* kfb = g_kf + (size_t)b * CHW;
    const float* qfb = g_qf + (size_t)b * CHW;

    __shared__ float SK[32][68];
    __shared__ float SQ[32][68];

    const int tid = threadIdx.x;
    const int tc  = (tid & 15) << 2;
    const int td  = (tid >> 4) << 2;

    float acc[4][4] = {};
    for (int l0 = s * 128; l0 < s * 128 + 128; l0 += 32) {
        __syncthreads();
        #pragma unroll
        for (int it = 0; it < 8; it++) {
            int idx = tid + it * 256;           // 0..2047
            int li = idx >> 6, c = idx & 63;
            int l = l0 + li;
            int pix = (3 * (l >> 5) + kh) * 96 + 3 * (l & 31) + kw;
            SK[li][c] = kfb[(size_t)pix * 64 + c];
            SQ[li][c] = qfb[(size_t)pix * 64 + c];
        }
        __syncthreads();
        #pragma unroll 8
        for (int li = 0; li < 32; li++) {
            float4 av = *reinterpret_cast<const float4*>(&SK[li][tc]);
            float4 bv = *reinterpret_cast<const float4*>(&SQ[li][td]);
            float a[4]  = {av.x, av.y, av.z, av.w};
            float bb[4] = {bv.x, bv.y, bv.z, bv.w};
            #pragma unroll
            for (int i = 0; i < 4; i++)
                #pragma unroll
                for (int j = 0; j < 4; j++)
                    acc[i][j] = fmaf(a[i], bb[j], acc[i][j]);
        }
    }
    const float sc = 1.0f / 24.0f;
    #pragma unroll
    for (int j = 0; j < 4; j++) {
        float* ap = g_sc[s] + ((size_t)(b * C + td + j)) * KK + k;
        #pragma unroll
        for (int i = 0; i < 4; i++)
            ap[(tc + i) * 9] = acc[i][j] * sc;
    }
}

// ---------------------------------------------------------------------------
// Reduce partials + softmax; write dyn weights w9d[b][k][d][c] (tf32).
// ---------------------------------------------------------------------------
__global__ void __launch_bounds__(256) softmax_kernel()
{
    const int row  = blockIdx.x * 8 + (threadIdx.x >> 5);   // b*64 + d
    const int lane = threadIdx.x & 31;
    const int b = row >> 6, d = row & 63;
    const size_t off = (size_t)row * KK;

    float v[18];
    float m = -3.4e38f;
    #pragma unroll
    for (int i = 0; i < 18; i++) {
        int idx = lane + i * 32;
        float t = 0.f;
        #pragma unroll
        for (int s = 0; s < NSLICE; s++) t += g_sc[s][off + idx];
        v[i] = t;
        m = fmaxf(m, t);
    }
    #pragma unroll
    for (int o = 16; o > 0; o >>= 1) m = fmaxf(m, __shfl_xor_sync(0xffffffffu, m, o));
    float ss = 0.f;
    #pragma unroll
    for (int i = 0; i < 18; i++) { v[i] = __expf(v[i] - m); ss += v[i]; }
    #pragma unroll
    for (int o = 16; o > 0; o >>= 1) ss += __shfl_xor_sync(0xffffffffu, ss, o);
    float inv = 1.0f / ss;
    #pragma unroll
    for (int i = 0; i < 18; i++) {
        int idx = lane + i * 32;           // idx = c*9 + k
        int c = idx / 9, k = idx - c * 9;
        g_w9d[(((size_t)b * 9 + k) * 64 + d) * 64 + c] = tf32r(v[i] * inv);
    }
}

extern "C" void kernel_launch(void* const* d_in, const int* in_sizes, int n_in,
                              void* d_out, int out_size)
{
    const float* x1 = (const float*)d_in[0];
    const float* x2 = (const float*)d_in[1];
    const float* w1 = (const float*)d_in[2];
    const float* w2 = (const float*)d_in[3];
    const float* w3 = (const float*)d_in[4];
    float* out = (float*)d_out;

    cudaFuncSetAttribute(conv_tc_kernel,
                         cudaFuncAttributeMaxDynamicSharedMemorySize, SMEM_DYN);

    prep_w9s_kernel<<<(3 * 9 * 4096 + 255) / 256, 256>>>(w1, w2, w3);
    conv_tc_kernel<<<dim3(12, 16, 3), 256, SMEM_DYN>>>(x1, x2, out, 0);
    scores_kernel<<<dim3(9, 16, NSLICE), 256>>>();
    softmax_kernel<<<128, 256>>>();
    conv_tc_kernel<<<dim3(12, 16, 1), 256, SMEM_DYN>>>(x1, x2, out, 1);
}

// round 9
// speedup vs baseline: 1.1482x; 1.1481x over previous
#include <cuda_runtime.h>
#include <cstdint>

#define NB   16
#define C    64
#define HWSZ 9216
#define CHW  589824
#define KK   576
#define NSLICE 8

// Scratch (static device arrays). Feature maps NHWC: [b][px][c].
__device__ float g_kf[NB * CHW];
__device__ float g_qf[NB * CHW];
__device__ float g_vf[NB * CHW];
__device__ float g_sc[NSLICE][NB * C * KK];
__device__ float g_w9s[3 * 9 * 64 * 64];   // [z][k9][cout][cin], tf32-rounded
__device__ float g_w9d[NB * 9 * 64 * 64];  // [b][k9][cout][cin], tf32-rounded

// tcgen05 is arch-SPECIFIC: only emit in the sm_103a/sm_100a pass.
#if defined(__CUDA_ARCH_FEAT_SM103_ALL) || defined(__CUDA_ARCH_FEAT_SM100_ALL) \
    || (defined(__CUDA_ARCH_SPECIFIC__) && (__CUDA_ARCH_SPECIFIC__ >= 1000))
#define HAS_TCGEN05 1
#else
#define HAS_TCGEN05 0
#endif

__device__ __forceinline__ float tf32r(float x) {
    uint32_t u;
    asm("cvt.rna.tf32.f32 %0, %1;" : "=r"(u) : "f"(x));
    return __uint_as_float(u);
}

#if HAS_TCGEN05
__device__ __forceinline__ uint32_t smem_u32(const void* p) {
    uint32_t a;
    asm("{ .reg .u64 t; cvta.to.shared.u64 t, %1; cvt.u32.u64 %0, t; }"
        : "=r"(a) : "l"(p));
    return a;
}
__device__ __forceinline__ uint32_t elect_one() {
    uint32_t pred;
    asm volatile("{\n\t.reg .pred p;\n\telect.sync _|p, 0xFFFFFFFF;\n\t"
                 "selp.b32 %0, 1, 0, p;\n\t}" : "=r"(pred));
    return pred;
}

#define MBARRIER_INIT(addr, cnt) \
    asm volatile("mbarrier.init.shared.b64 [%0], %1;" :: "r"(addr), "r"(cnt) : "memory")
#define MBARRIER_INVAL(addr) \
    asm volatile("mbarrier.inval.shared.b64 [%0];" :: "r"(addr) : "memory")
#define MBARRIER_WAIT_PARITY(addr, par) do {                                   \
    uint32_t _m = (addr), _p = (par), _d;                                      \
    asm volatile("{\n\t.reg .pred p;\n\t"                                      \
        "mbarrier.try_wait.parity.acquire.cta.shared::cta.b64 p, [%1], %2;\n\t"\
        "selp.b32 %0, 1, 0, p;\n\t}" : "=r"(_d) : "r"(_m), "r"(_p) : "memory");\
    if (!_d) {                                                                 \
        asm volatile("{\n\t.reg .pred P1;\n\tWL%=:\n\t"                        \
        "mbarrier.try_wait.parity.acquire.cta.shared::cta.b64 P1, [%0], %1, 0x989680;\n\t" \
        "@P1 bra.uni WD%=;\n\tbra.uni WL%=;\n\tWD%=:\n\t}"                     \
        :: "r"(_m), "r"(_p) : "memory");                                       \
    } } while (0)

#define TCGEN05_ALLOC(res, n) \
    asm volatile("tcgen05.alloc.cta_group::1.sync.aligned.shared::cta.b32 [%0], %1;" \
                 :: "r"(res), "r"((uint32_t)(n)) : "memory")
#define TCGEN05_DEALLOC(t, n) \
    asm volatile("tcgen05.dealloc.cta_group::1.sync.aligned.b32 %0, %1;" :: "r"(t), "r"((uint32_t)(n)))
#define TCGEN05_RELINQ() \
    asm volatile("tcgen05.relinquish_alloc_permit.cta_group::1.sync.aligned;")
#define TCGEN05_COMMIT(mb) \
    asm volatile("tcgen05.commit.cta_group::1.mbarrier::arrive::one.shared::cluster.b64 [%0];" \
                 :: "r"(mb) : "memory")
#define TCGEN05_FENCE_AFTER()  asm volatile("tcgen05.fence::after_thread_sync;" ::: "memory")
#define TCGEN05_FENCE_BEFORE() asm volatile("tcgen05.fence::before_thread_sync;" ::: "memory")
#define TCGEN05_WAIT_LD()      asm volatile("tcgen05.wait::ld.sync.aligned;" ::: "memory")
#define FENCE_ASYNC_SHARED()   asm volatile("fence.proxy.async.shared::cta;" ::: "memory")

#define TCGEN05_LD_X32(r, ta) \
    asm volatile("tcgen05.ld.sync.aligned.32x32b.x32.b32 "                     \
        "{%0,%1,%2,%3,%4,%5,%6,%7,%8,%9,%10,%11,%12,%13,%14,%15,"             \
        "%16,%17,%18,%19,%20,%21,%22,%23,%24,%25,%26,%27,%28,%29,%30,%31}, [%32];" \
        : "=r"((r)[0]),"=r"((r)[1]),"=r"((r)[2]),"=r"((r)[3]),                 \
          "=r"((r)[4]),"=r"((r)[5]),"=r"((r)[6]),"=r"((r)[7]),                 \
          "=r"((r)[8]),"=r"((r)[9]),"=r"((r)[10]),"=r"((r)[11]),               \
          "=r"((r)[12]),"=r"((r)[13]),"=r"((r)[14]),"=r"((r)[15]),             \
          "=r"((r)[16]),"=r"((r)[17]),"=r"((r)[18]),"=r"((r)[19]),             \
          "=r"((r)[20]),"=r"((r)[21]),"=r"((r)[22]),"=r"((r)[23]),             \
          "=r"((r)[24]),"=r"((r)[25]),"=r"((r)[26]),"=r"((r)[27]),             \
          "=r"((r)[28]),"=r"((r)[29]),"=r"((r)[30]),"=r"((r)[31])              \
        : "r"(ta))

__device__ __forceinline__ void mma_tf32(uint32_t d, uint64_t a, uint64_t b,
                                         uint32_t idesc, uint32_t en) {
    asm volatile("{\n\t.reg .pred p;\n\tsetp.ne.u32 p, %5, 0;\n\t"
                 "tcgen05.mma.cta_group::1.kind::tf32 [%0], %1, %2, %3, {%4,%4,%4,%4}, p;\n\t}"
                 :: "r"(d), "l"(a), "l"(b), "r"(idesc), "r"(0u), "r"(en) : "memory");
}

static __device__ __forceinline__ uint64_t mk_desc(uint32_t addr) {
    return ((uint64_t)2 << 61) | ((uint64_t)1 << 46) | ((uint64_t)64 << 32)
         | ((uint64_t)1 << 16) | (uint64_t)((addr >> 4) & 0x3FFF);
}
__device__ __forceinline__ uint32_t sw128(uint32_t off) { return off ^ ((off >> 3) & 0x70); }

// idesc: D=F32, a=TF32, b=TF32, K-major both, N=64, M=128
#define IDESC_TF32 ((1u<<4) | (2u<<7) | (2u<<10) | ((64u/8u)<<17) | ((128u/16u)<<24))
#endif  // HAS_TCGEN05

#define NBUF       6
#define ABUF_BYTES 16384              // 128 rows * 128B
#define BREG_OFF   (NBUF * ABUF_BYTES)
#define SMEM_DYN   (1024 + BREG_OFF + 9 * 8192)

// ---------------------------------------------------------------------------
// Tensor-core conv. Grid (12, 16, z). 256 threads.
// A-row loads are register-pipelined: LDG issued one MMA-pass ahead; only the
// STS (after the ring-buffer wait) sits on the critical path.
// ---------------------------------------------------------------------------
__global__ void __launch_bounds__(256, 1)
conv_tc_kernel(const float* __restrict__ x1, const float* __restrict__ x2,
               float* __restrict__ out, int dyn)
{
#if HAS_TCGEN05
    extern __shared__ char smem[];
    __shared__ uint32_t s_tmem;
    __shared__ alignas(16) unsigned long long s_mbar[4];

    const int tid = threadIdx.x;
    const int wid = tid >> 5, lid = tid & 31;
    const int r0  = blockIdx.x * 8;
    const int b   = blockIdx.y;
    const int z   = blockIdx.z;

    uint32_t sm0 = smem_u32(smem);
    uint32_t Ab  = (sm0 + 1023) & ~1023u;
    uint32_t Bb  = Ab + BREG_OFF;
    char* Abp = smem + (Ab - sm0);
    char* Bbp = smem + (Bb - sm0);
    uint32_t mb[4] = { smem_u32(&s_mbar[0]), smem_u32(&s_mbar[1]),
                       smem_u32(&s_mbar[2]), smem_u32(&s_mbar[3]) };

    if (wid == 0) TCGEN05_ALLOC(smem_u32(&s_tmem), 512);
    if (tid < 4) MBARRIER_INIT(mb[tid], 1);
    // zero constant halo rows (row 0 = col -1; rows 97..127) of all buffers
    for (int i = tid; i < NBUF * 32 * 32; i += 256) {
        int buf = i >> 10, rr = i & 1023, row = rr >> 5, wd = rr & 31;
        int prow = (row == 0) ? 0 : (96 + row);
        *(float*)(Abp + buf * ABUF_BYTES + prow * 128 + wd * 4) = 0.f;
    }
    if (wid == 0) TCGEN05_RELINQ();
    __syncthreads();
    const uint32_t tmem = s_tmem;

    const float* xsrc = dyn ? nullptr : ((z == 1) ? x2 : x1);

    // --- register-staged A-row load/store ---
    auto issue_ldg = [&](float4* v, int ri, int h) {
        bool valid = ((unsigned)ri < 96u);
        if (!dyn) {
            const float* src = xsrc + (size_t)b * CHW;
            #pragma unroll
            for (int it = 0; it < 3; it++) {
                int idx = it * 256 + tid;
                int cin = idx / 24, c4 = idx % 24;
                v[it] = valid
                    ? *(const float4*)(src + (size_t)(h * 32 + cin) * HWSZ
                                       + ri * 96 + c4 * 4)
                    : make_float4(0.f, 0.f, 0.f, 0.f);
            }
        } else {
            const float* src = g_vf + (size_t)b * CHW;
            #pragma unroll
            for (int it = 0; it < 3; it++) {
                int idx = it * 256 + tid;
                int col = idx >> 3, ci4 = idx & 7;
                v[it] = valid
                    ? *(const float4*)(src + (size_t)(ri * 96 + col) * 64
                                       + h * 32 + ci4 * 4)
                    : make_float4(0.f, 0.f, 0.f, 0.f);
            }
        }
    };
    auto store_a = [&](char* abuf, const float4* v) {
        if (!dyn) {
            #pragma unroll
            for (int it = 0; it < 3; it++) {
                int idx = it * 256 + tid;
                int cin = idx / 24, c4 = idx % 24;
                float vv[4] = {v[it].x, v[it].y, v[it].z, v[it].w};
                #pragma unroll
                for (int j = 0; j < 4; j++)
                    *(float*)(abuf + sw128((c4 * 4 + j + 1) * 128 + cin * 4))
                        = tf32r(vv[j]);
            }
        } else {
            #pragma unroll
            for (int it = 0; it < 3; it++) {
                int idx = it * 256 + tid;
                int col = idx >> 3, ci4 = idx & 7;
                *(float4*)(abuf + sw128((col + 1) * 128 + ci4 * 16)) =
                    make_float4(tf32r(v[it].x), tf32r(v[it].y),
                                tf32r(v[it].z), tf32r(v[it].w));
            }
        }
    };

    int ncommit = 0;
    for (int h = 0; h < 2; h++) {
        // issue all prologue LDGs first (latency overlaps drain + B load)
        float4 v0[3], v1[3], v2[3], pf[3];
        issue_ldg(v0, r0 - 1, h);
        issue_ldg(v1, r0,     h);
        issue_ldg(v2, r0 + 1, h);
        issue_ldg(pf, r0 + 2, h);

        if (ncommit > 0) {       // B tile + bufs 0..2 reused: drain all MMAs
            int k = ncommit - 1;
            MBARRIER_WAIT_PARITY(mb[k & 3], (k >> 2) & 1);
        }
        // ---- load B: 9 shifts x 64 cout x 32 cin ----
        #pragma unroll
        for (int it = 0; it < 18; it++) {
            int idx = it * 256 + tid;
            int k9 = idx >> 9, r2 = idx & 511, co = r2 >> 3, ci4 = r2 & 7;
            const float* src = dyn
                ? &g_w9d[(((size_t)b * 9 + k9) * 64 + co) * 64 + h * 32 + ci4 * 4]
                : &g_w9s[(((size_t)z * 9 + k9) * 64 + co) * 64 + h * 32 + ci4 * 4];
            float4 v = *(const float4*)src;
            *(float4*)(Bbp + k9 * 8192 + sw128(co * 128 + ci4 * 16)) = v;
        }
        store_a(Abp + 0 * ABUF_BYTES, v0);
        store_a(Abp + 1 * ABUF_BYTES, v1);
        store_a(Abp + 2 * ABUF_BYTES, v2);
        __syncthreads();
        FENCE_ASYNC_SHARED();

        for (int r = 0; r < 8; r++) {
            if (wid == 0 && elect_one()) {
                #pragma unroll
                for (int s = 0; s < 9; s++) {
                    int kh = s / 3, kw = s - kh * 3;
                    int buf = (r + kh) % NBUF;
                    uint64_t ad = mk_desc(Ab + buf * ABUF_BYTES + kw * 128);
                    uint64_t bd = mk_desc(Bb + s * 8192);
                    #pragma unroll
                    for (int ks = 0; ks < 4; ks++)
                        mma_tf32(tmem + r * 64, ad + ks * 2, bd + ks * 2,
                                 IDESC_TF32, (h | s | ks) != 0);
                }
                TCGEN05_COMMIT(mb[ncommit & 3]);
            }
            ncommit++;
            if (r < 7) {
                // buffer (r+3)%NBUF last read by MMA pass r-3 (3 passes deep)
                if (r >= 3) {
                    int k = ncommit - 4;
                    MBARRIER_WAIT_PARITY(mb[k & 3], (k >> 2) & 1);
                }
                store_a(Abp + ((r + 3) % NBUF) * ABUF_BYTES, pf);
                if (r < 6) issue_ldg(pf, r0 + r + 3, h);   // next pass's row
                __syncthreads();
                FENCE_ASYNC_SHARED();
            }
        }
    }
    { int k = ncommit - 1; MBARRIER_WAIT_PARITY(mb[k & 3], (k >> 2) & 1); }
    TCGEN05_FENCE_AFTER();

    // ---- epilogue: 6 warps; warps 0-2 cols 0..31, warps 4-6 cols 32..63 ----
    if ((wid & 3) < 3) {
        int half = wid >> 2;            // 0 or 1
        int px   = (wid & 3) * 32 + lid;
        for (int r = 0; r < 8; r++) {
            uint32_t d0[32];
            TCGEN05_LD_X32(d0, tmem + r * 64 + half * 32);
            TCGEN05_WAIT_LD();
            if (!dyn) {
                float* dst = ((z == 0) ? g_kf : (z == 1) ? g_qf : g_vf)
                           + ((size_t)b * HWSZ + (size_t)(r0 + r) * 96 + px) * 64
                           + half * 32;
                #pragma unroll
                for (int q = 0; q < 8; q++)
                    *(float4*)(dst + q * 4) = make_float4(
                        __uint_as_float(d0[q*4]),   __uint_as_float(d0[q*4+1]),
                        __uint_as_float(d0[q*4+2]), __uint_as_float(d0[q*4+3]));
            } else {
                float* dst = out + (size_t)b * CHW + (size_t)(r0 + r) * 96 + px
                           + (size_t)half * 32 * HWSZ;
                #pragma unroll
                for (int c = 0; c < 32; c++)
                    dst[(size_t)c * HWSZ] = __uint_as_float(d0[c]);
            }
        }
    }
    TCGEN05_FENCE_BEFORE();
    __syncthreads();
    if (tid < 4) MBARRIER_INVAL(mb[tid]);
    __syncthreads();
    if (wid == 0) TCGEN05_DEALLOC(tmem, 512);
#endif  // HAS_TCGEN05
}

// ---------------------------------------------------------------------------
// Static-weight transpose + tf32 round: w9s[z][k][cout][cin]
// ---------------------------------------------------------------------------
__global__ void __launch_bounds__(256) prep_w9s_kernel(
    const float* __restrict__ w1, const float* __restrict__ w2,
    const float* __restrict__ w3)
{
    int idx = blockIdx.x * 256 + threadIdx.x;
    if (idx >= 3 * 9 * 4096) return;
    int z = idx / 36864, rem = idx - z * 36864;
    int k = rem >> 12, r2 = rem & 4095, co = r2 >> 6, ci = r2 & 63;
    const float* w = (z == 0) ? w1 : (z == 1) ? w2 : w3;
    g_w9s[idx] = tf32r(w[co * 576 + ci * 9 + k]);
}

// ---------------------------------------------------------------------------
// scores partials (NHWC). Grid (9, 16, NSLICE), block 256. 128 L per slice.
// ---------------------------------------------------------------------------
__global__ void __launch_bounds__(256) scores_kernel()
{
    const int k  = blockIdx.x, b = blockIdx.y, s = blockIdx.z;
    const int kh = k / 3, kw = k % 3;
    const float* kfb = g_kf + (size_t)b * CHW;
    const float* qfb = g_qf + (size_t)b * CHW;

    __shared__ float SK[32][68];
    __shared__ float SQ[32][68];

    const int tid = threadIdx.x;
    const int tc  = (tid & 15) << 2;
    const int td  = (tid >> 4) << 2;

    float acc[4][4] = {};
    for (int l0 = s * 128; l0 < s * 128 + 128; l0 += 32) {
        __syncthreads();
        #pragma unroll
        for (int it = 0; it < 8; it++) {
            int idx = tid + it * 256;           // 0..2047
            int li = idx >> 6, c = idx & 63;
            int l = l0 + li;
            int pix = (3 * (l >> 5) + kh) * 96 + 3 * (l & 31) + kw;
            SK[li][c] = kfb[(size_t)pix * 64 + c];
            SQ[li][c] = qfb[(size_t)pix * 64 + c];
        }
        __syncthreads();
        #pragma unroll 8
        for (int li = 0; li < 32; li++) {
            float4 av = *reinterpret_cast<const float4*>(&SK[li][tc]);
            float4 bv = *reinterpret_cast<const float4*>(&SQ[li][td]);
            float a[4]  = {av.x, av.y, av.z, av.w};
            float bb[4] = {bv.x, bv.y, bv.z, bv.w};
            #pragma unroll
            for (int i = 0; i < 4; i++)
                #pragma unroll
                for (int j = 0; j < 4; j++)
                    acc[i][j] = fmaf(a[i], bb[j], acc[i][j]);
        }
    }
    const float sc = 1.0f / 24.0f;
    #pragma unroll
    for (int j = 0; j < 4; j++) {
        float* ap = g_sc[s] + ((size_t)(b * C + td + j)) * KK + k;
        #pragma unroll
        for (int i = 0; i < 4; i++)
            ap[(tc + i) * 9] = acc[i][j] * sc;
    }
}

// ---------------------------------------------------------------------------
// Reduce partials + softmax; write dyn weights w9d[b][k][d][c] (tf32).
// ---------------------------------------------------------------------------
__global__ void __launch_bounds__(256) softmax_kernel()
{
    const int row  = blockIdx.x * 8 + (threadIdx.x >> 5);   // b*64 + d
    const int lane = threadIdx.x & 31;
    const int b = row >> 6, d = row & 63;
    const size_t off = (size_t)row * KK;

    float v[18];
    float m = -3.4e38f;
    #pragma unroll
    for (int i = 0; i < 18; i++) {
        int idx = lane + i * 32;
        float t = 0.f;
        #pragma unroll
        for (int s = 0; s < NSLICE; s++) t += g_sc[s][off + idx];
        v[i] = t;
        m = fmaxf(m, t);
    }
    #pragma unroll
    for (int o = 16; o > 0; o >>= 1) m = fmaxf(m, __shfl_xor_sync(0xffffffffu, m, o));
    float ss = 0.f;
    #pragma unroll
    for (int i = 0; i < 18; i++) { v[i] = __expf(v[i] - m); ss += v[i]; }
    #pragma unroll
    for (int o = 16; o > 0; o >>= 1) ss += __shfl_xor_sync(0xffffffffu, ss, o);
    float inv = 1.0f / ss;
    #pragma unroll
    for (int i = 0; i < 18; i++) {
        int idx = lane + i * 32;           // idx = c*9 + k
        int c = idx / 9, k = idx - c * 9;
        g_w9d[(((size_t)b * 9 + k) * 64 + d) * 64 + c] = tf32r(v[i] * inv);
    }
}

extern "C" void kernel_launch(void* const* d_in, const int* in_sizes, int n_in,
                              void* d_out, int out_size)
{
    const float* x1 = (const float*)d_in[0];
    const float* x2 = (const float*)d_in[1];
    const float* w1 = (const float*)d_in[2];
    const float* w2 = (const float*)d_in[3];
    const float* w3 = (const float*)d_in[4];
    float* out = (float*)d_out;

    cudaFuncSetAttribute(conv_tc_kernel,
                         cudaFuncAttributeMaxDynamicSharedMemorySize, SMEM_DYN);

    prep_w9s_kernel<<<(3 * 9 * 4096 + 255) / 256, 256>>>(w1, w2, w3);
    conv_tc_kernel<<<dim3(12, 16, 3), 256, SMEM_DYN>>>(x1, x2, out, 0);
    scores_kernel<<<dim3(9, 16, NSLICE), 256>>>();
    softmax_kernel<<<128, 256>>>();
    conv_tc_kernel<<<dim3(12, 16, 1), 256, SMEM_DYN>>>(x1, x2, out, 1);
}

// round 10
// speedup vs baseline: 1.1755x; 1.0238x over previous
#include <cuda_runtime.h>
#include <cstdint>

#define NB   16
#define C    64
#define HWSZ 9216
#define CHW  589824
#define KK   576
#define NSLICE 8

// Scratch (static device arrays). Feature maps NHWC: [b][px][c].
__device__ float g_kf[NB * CHW];
__device__ float g_qf[NB * CHW];
__device__ float g_vf[NB * CHW];
__device__ float g_sc[NSLICE][NB * C * KK];
__device__ float g_w9s[3 * 9 * 64 * 64];   // [z][k9][cout][cin], tf32-rounded
__device__ float g_w9d[NB * 9 * 64 * 64];  // [b][k9][cout][cin], tf32-rounded

// tcgen05 is arch-SPECIFIC: only emit in the sm_103a/sm_100a pass.
#if defined(__CUDA_ARCH_FEAT_SM103_ALL) || defined(__CUDA_ARCH_FEAT_SM100_ALL) \
    || (defined(__CUDA_ARCH_SPECIFIC__) && (__CUDA_ARCH_SPECIFIC__ >= 1000))
#define HAS_TCGEN05 1
#else
#define HAS_TCGEN05 0
#endif

__device__ __forceinline__ float tf32r(float x) {
    uint32_t u;
    asm("cvt.rna.tf32.f32 %0, %1;" : "=r"(u) : "f"(x));
    return __uint_as_float(u);
}

#if HAS_TCGEN05
__device__ __forceinline__ uint32_t smem_u32(const void* p) {
    uint32_t a;
    asm("{ .reg .u64 t; cvta.to.shared.u64 t, %1; cvt.u32.u64 %0, t; }"
        : "=r"(a) : "l"(p));
    return a;
}
__device__ __forceinline__ uint32_t elect_one() {
    uint32_t pred;
    asm volatile("{\n\t.reg .pred p;\n\telect.sync _|p, 0xFFFFFFFF;\n\t"
                 "selp.b32 %0, 1, 0, p;\n\t}" : "=r"(pred));
    return pred;
}

#define MBARRIER_INIT(addr, cnt) \
    asm volatile("mbarrier.init.shared.b64 [%0], %1;" :: "r"(addr), "r"(cnt) : "memory")
#define MBARRIER_INVAL(addr) \
    asm volatile("mbarrier.inval.shared.b64 [%0];" :: "r"(addr) : "memory")
#define MBARRIER_WAIT_PARITY(addr, par) do {                                   \
    uint32_t _m = (addr), _p = (par), _d;                                      \
    asm volatile("{\n\t.reg .pred p;\n\t"                                      \
        "mbarrier.try_wait.parity.acquire.cta.shared::cta.b64 p, [%1], %2;\n\t"\
        "selp.b32 %0, 1, 0, p;\n\t}" : "=r"(_d) : "r"(_m), "r"(_p) : "memory");\
    if (!_d) {                                                                 \
        asm volatile("{\n\t.reg .pred P1;\n\tWL%=:\n\t"                        \
        "mbarrier.try_wait.parity.acquire.cta.shared::cta.b64 P1, [%0], %1, 0x989680;\n\t" \
        "@P1 bra.uni WD%=;\n\tbra.uni WL%=;\n\tWD%=:\n\t}"                     \
        :: "r"(_m), "r"(_p) : "memory");                                       \
    } } while (0)

#define TCGEN05_ALLOC(res, n) \
    asm volatile("tcgen05.alloc.cta_group::1.sync.aligned.shared::cta.b32 [%0], %1;" \
                 :: "r"(res), "r"((uint32_t)(n)) : "memory")
#define TCGEN05_DEALLOC(t, n) \
    asm volatile("tcgen05.dealloc.cta_group::1.sync.aligned.b32 %0, %1;" :: "r"(t), "r"((uint32_t)(n)))
#define TCGEN05_RELINQ() \
    asm volatile("tcgen05.relinquish_alloc_permit.cta_group::1.sync.aligned;")
#define TCGEN05_COMMIT(mb) \
    asm volatile("tcgen05.commit.cta_group::1.mbarrier::arrive::one.shared::cluster.b64 [%0];" \
                 :: "r"(mb) : "memory")
#define TCGEN05_FENCE_AFTER()  asm volatile("tcgen05.fence::after_thread_sync;" ::: "memory")
#define TCGEN05_FENCE_BEFORE() asm volatile("tcgen05.fence::before_thread_sync;" ::: "memory")
#define TCGEN05_WAIT_LD()      asm volatile("tcgen05.wait::ld.sync.aligned;" ::: "memory")
#define FENCE_ASYNC_SHARED()   asm volatile("fence.proxy.async.shared::cta;" ::: "memory")

#define TCGEN05_LD_X32(r, ta) \
    asm volatile("tcgen05.ld.sync.aligned.32x32b.x32.b32 "                     \
        "{%0,%1,%2,%3,%4,%5,%6,%7,%8,%9,%10,%11,%12,%13,%14,%15,"             \
        "%16,%17,%18,%19,%20,%21,%22,%23,%24,%25,%26,%27,%28,%29,%30,%31}, [%32];" \
        : "=r"((r)[0]),"=r"((r)[1]),"=r"((r)[2]),"=r"((r)[3]),                 \
          "=r"((r)[4]),"=r"((r)[5]),"=r"((r)[6]),"=r"((r)[7]),                 \
          "=r"((r)[8]),"=r"((r)[9]),"=r"((r)[10]),"=r"((r)[11]),               \
          "=r"((r)[12]),"=r"((r)[13]),"=r"((r)[14]),"=r"((r)[15]),             \
          "=r"((r)[16]),"=r"((r)[17]),"=r"((r)[18]),"=r"((r)[19]),             \
          "=r"((r)[20]),"=r"((r)[21]),"=r"((r)[22]),"=r"((r)[23]),             \
          "=r"((r)[24]),"=r"((r)[25]),"=r"((r)[26]),"=r"((r)[27]),             \
          "=r"((r)[28]),"=r"((r)[29]),"=r"((r)[30]),"=r"((r)[31])              \
        : "r"(ta))

__device__ __forceinline__ void mma_tf32(uint32_t d, uint64_t a, uint64_t b,
                                         uint32_t idesc, uint32_t en) {
    asm volatile("{\n\t.reg .pred p;\n\tsetp.ne.u32 p, %5, 0;\n\t"
                 "tcgen05.mma.cta_group::1.kind::tf32 [%0], %1, %2, %3, {%4,%4,%4,%4}, p;\n\t}"
                 :: "r"(d), "l"(a), "l"(b), "r"(idesc), "r"(0u), "r"(en) : "memory");
}

static __device__ __forceinline__ uint64_t mk_desc(uint32_t addr) {
    return ((uint64_t)2 << 61) | ((uint64_t)1 << 46) | ((uint64_t)64 << 32)
         | ((uint64_t)1 << 16) | (uint64_t)((addr >> 4) & 0x3FFF);
}
__device__ __forceinline__ uint32_t sw128(uint32_t off) { return off ^ ((off >> 3) & 0x70); }

// idesc: D=F32, a=TF32, b=TF32, K-major both, N=64, M=128
#define IDESC_TF32 ((1u<<4) | (2u<<7) | (2u<<10) | ((64u/8u)<<17) | ((128u/16u)<<24))
#endif  // HAS_TCGEN05

#define NBUF       6
#define ABUF_BYTES 16384              // 128 rows * 128B
#define BREG_OFF   (NBUF * ABUF_BYTES)
#define SMEM_DYN   (1024 + BREG_OFF + 9 * 8192)

// ---------------------------------------------------------------------------
// Tensor-core conv. Grid (12, 16, z). 256 threads.
// A-row loads register-pipelined (LDG one pass ahead); static-conv staging is
// px-major so STS.128 is bank-conflict-free under SW128.
// ---------------------------------------------------------------------------
__global__ void __launch_bounds__(256, 1)
conv_tc_kernel(const float* __restrict__ x1, const float* __restrict__ x2,
               float* __restrict__ out, int dyn)
{
#if HAS_TCGEN05
    extern __shared__ char smem[];
    __shared__ uint32_t s_tmem;
    __shared__ alignas(16) unsigned long long s_mbar[4];

    const int tid = threadIdx.x;
    const int wid = tid >> 5, lid = tid & 31;
    const int r0  = blockIdx.x * 8;
    const int b   = blockIdx.y;
    const int z   = blockIdx.z;

    uint32_t sm0 = smem_u32(smem);
    uint32_t Ab  = (sm0 + 1023) & ~1023u;
    uint32_t Bb  = Ab + BREG_OFF;
    char* Abp = smem + (Ab - sm0);
    char* Bbp = smem + (Bb - sm0);
    uint32_t mb[4] = { smem_u32(&s_mbar[0]), smem_u32(&s_mbar[1]),
                       smem_u32(&s_mbar[2]), smem_u32(&s_mbar[3]) };

    if (wid == 0) TCGEN05_ALLOC(smem_u32(&s_tmem), 512);
    if (tid < 4) MBARRIER_INIT(mb[tid], 1);
    // zero constant halo rows (row 0 = col -1; rows 97..127) of all buffers
    for (int i = tid; i < NBUF * 32 * 32; i += 256) {
        int buf = i >> 10, rr = i & 1023, row = rr >> 5, wd = rr & 31;
        int prow = (row == 0) ? 0 : (96 + row);
        *(float*)(Abp + buf * ABUF_BYTES + prow * 128 + wd * 4) = 0.f;
    }
    if (wid == 0) TCGEN05_RELINQ();
    __syncthreads();
    const uint32_t tmem = s_tmem;

    const float* xsrc = dyn ? nullptr : ((z == 1) ? x2 : x1);

    // --- register-staged A-row load/store ---
    // static: idx -> px = idx%96, cg = idx/96 (cin group of 4);
    //         4 coalesced scalar LDGs (stride HWSZ), one STS.128.
    auto issue_ldg = [&](float4* v, int ri, int h) {
        bool valid = ((unsigned)ri < 96u);
        if (!dyn) {
            const float* src = xsrc + (size_t)b * CHW + (size_t)ri * 96;
            #pragma unroll
            for (int it = 0; it < 3; it++) {
                int idx = it * 256 + tid;
                int px = idx % 96, cg = idx / 96;
                if (valid) {
                    const float* p = src + (size_t)(h * 32 + cg * 4) * HWSZ + px;
                    v[it] = make_float4(p[0], p[HWSZ], p[2 * HWSZ], p[3 * HWSZ]);
                } else {
                    v[it] = make_float4(0.f, 0.f, 0.f, 0.f);
                }
            }
        } else {
            const float* src = g_vf + (size_t)b * CHW;
            #pragma unroll
            for (int it = 0; it < 3; it++) {
                int idx = it * 256 + tid;
                int col = idx >> 3, ci4 = idx & 7;
                v[it] = valid
                    ? *(const float4*)(src + (size_t)(ri * 96 + col) * 64
                                       + h * 32 + ci4 * 4)
                    : make_float4(0.f, 0.f, 0.f, 0.f);
            }
        }
    };
    auto store_a = [&](char* abuf, const float4* v) {
        if (!dyn) {
            #pragma unroll
            for (int it = 0; it < 3; it++) {
                int idx = it * 256 + tid;
                int px = idx % 96, cg = idx / 96;
                *(float4*)(abuf + sw128((px + 1) * 128 + cg * 16)) =
                    make_float4(tf32r(v[it].x), tf32r(v[it].y),
                                tf32r(v[it].z), tf32r(v[it].w));
            }
        } else {
            #pragma unroll
            for (int it = 0; it < 3; it++) {
                int idx = it * 256 + tid;
                int col = idx >> 3, ci4 = idx & 7;
                *(float4*)(abuf + sw128((col + 1) * 128 + ci4 * 16)) =
                    make_float4(tf32r(v[it].x), tf32r(v[it].y),
                                tf32r(v[it].z), tf32r(v[it].w));
            }
        }
    };

    int ncommit = 0;
    for (int h = 0; h < 2; h++) {
        // issue all prologue LDGs first (latency overlaps drain + B load)
        float4 v0[3], v1[3], v2[3], pf[3];
        issue_ldg(v0, r0 - 1, h);
        issue_ldg(v1, r0,     h);
        issue_ldg(v2, r0 + 1, h);
        issue_ldg(pf, r0 + 2, h);

        if (ncommit > 0) {       // B tile + bufs 0..2 reused: drain all MMAs
            int k = ncommit - 1;
            MBARRIER_WAIT_PARITY(mb[k & 3], (k >> 2) & 1);
        }
        // ---- load B: 9 shifts x 64 cout x 32 cin ----
        #pragma unroll
        for (int it = 0; it < 18; it++) {
            int idx = it * 256 + tid;
            int k9 = idx >> 9, r2 = idx & 511, co = r2 >> 3, ci4 = r2 & 7;
            const float* src = dyn
                ? &g_w9d[(((size_t)b * 9 + k9) * 64 + co) * 64 + h * 32 + ci4 * 4]
                : &g_w9s[(((size_t)z * 9 + k9) * 64 + co) * 64 + h * 32 + ci4 * 4];
            float4 v = *(const float4*)src;
            *(float4*)(Bbp + k9 * 8192 + sw128(co * 128 + ci4 * 16)) = v;
        }
        store_a(Abp + 0 * ABUF_BYTES, v0);
        store_a(Abp + 1 * ABUF_BYTES, v1);
        store_a(Abp + 2 * ABUF_BYTES, v2);
        __syncthreads();
        FENCE_ASYNC_SHARED();

        for (int r = 0; r < 8; r++) {
            if (wid == 0 && elect_one()) {
                #pragma unroll
                for (int s = 0; s < 9; s++) {
                    int kh = s / 3, kw = s - kh * 3;
                    int buf = (r + kh) % NBUF;
                    uint64_t ad = mk_desc(Ab + buf * ABUF_BYTES + kw * 128);
                    uint64_t bd = mk_desc(Bb + s * 8192);
                    #pragma unroll
                    for (int ks = 0; ks < 4; ks++)
                        mma_tf32(tmem + r * 64, ad + ks * 2, bd + ks * 2,
                                 IDESC_TF32, (h | s | ks) != 0);
                }
                TCGEN05_COMMIT(mb[ncommit & 3]);
            }
            ncommit++;
            if (r < 7) {
                // buffer (r+3)%NBUF last read by MMA pass r-3 (3 passes deep)
                if (r >= 3) {
                    int k = ncommit - 4;
                    MBARRIER_WAIT_PARITY(mb[k & 3], (k >> 2) & 1);
                }
                store_a(Abp + ((r + 3) % NBUF) * ABUF_BYTES, pf);
                if (r < 6) issue_ldg(pf, r0 + r + 3, h);   // next pass's row
                __syncthreads();
                FENCE_ASYNC_SHARED();
            }
        }
    }
    { int k = ncommit - 1; MBARRIER_WAIT_PARITY(mb[k & 3], (k >> 2) & 1); }
    TCGEN05_FENCE_AFTER();

    // ---- epilogue: 6 warps; warps 0-2 cols 0..31, warps 4-6 cols 32..63 ----
    if ((wid & 3) < 3) {
        int half = wid >> 2;            // 0 or 1
        int px   = (wid & 3) * 32 + lid;
        for (int r = 0; r < 8; r++) {
            uint32_t d0[32];
            TCGEN05_LD_X32(d0, tmem + r * 64 + half * 32);
            TCGEN05_WAIT_LD();
            if (!dyn) {
                float* dst = ((z == 0) ? g_kf : (z == 1) ? g_qf : g_vf)
                           + ((size_t)b * HWSZ + (size_t)(r0 + r) * 96 + px) * 64
                           + half * 32;
                #pragma unroll
                for (int q = 0; q < 8; q++)
                    *(float4*)(dst + q * 4) = make_float4(
                        __uint_as_float(d0[q*4]),   __uint_as_float(d0[q*4+1]),
                        __uint_as_float(d0[q*4+2]), __uint_as_float(d0[q*4+3]));
            } else {
                float* dst = out + (size_t)b * CHW + (size_t)(r0 + r) * 96 + px
                           + (size_t)half * 32 * HWSZ;
                #pragma unroll
                for (int c = 0; c < 32; c++)
                    dst[(size_t)c * HWSZ] = __uint_as_float(d0[c]);
            }
        }
    }
    TCGEN05_FENCE_BEFORE();
    __syncthreads();
    if (tid < 4) MBARRIER_INVAL(mb[tid]);
    __syncthreads();
    if (wid == 0) TCGEN05_DEALLOC(tmem, 512);
#endif  // HAS_TCGEN05
}

// ---------------------------------------------------------------------------
// Static-weight transpose + tf32 round: w9s[z][k][cout][cin]
// ---------------------------------------------------------------------------
__global__ void __launch_bounds__(256) prep_w9s_kernel(
    const float* __restrict__ w1, const float* __restrict__ w2,
    const float* __restrict__ w3)
{
    int idx = blockIdx.x * 256 + threadIdx.x;
    if (idx >= 3 * 9 * 4096) return;
    int z = idx / 36864, rem = idx - z * 36864;
    int k = rem >> 12, r2 = rem & 4095, co = r2 >> 6, ci = r2 & 63;
    const float* w = (z == 0) ? w1 : (z == 1) ? w2 : w3;
    g_w9s[idx] = tf32r(w[co * 576 + ci * 9 + k]);
}

// ---------------------------------------------------------------------------
// scores partials (NHWC). Grid (9, 16, NSLICE), block 256. 128 L per slice.
// ---------------------------------------------------------------------------
__global__ void __launch_bounds__(256) scores_kernel()
{
    const int k  = blockIdx.x, b = blockIdx.y, s = blockIdx.z;
    const int kh = k / 3, kw = k % 3;
    const float* kfb = g_kf + (size_t)b * CHW;
    const float* qfb = g_qf + (size_t)b * CHW;

    __shared__ float SK[32][68];
    __shared__ float SQ[32][68];

    const int tid = threadIdx.x;
    const int tc  = (tid & 15) << 2;
    const int td  = (tid >> 4) << 2;

    float acc[4][4] = {};
    for (int l0 = s * 128; l0 < s * 128 + 128; l0 += 32) {
        __syncthreads();
        #pragma unroll
        for (int it = 0; it < 8; it++) {
            int idx = tid + it * 256;           // 0..2047
            int li = idx >> 6, c = idx & 63;
            int l = l0 + li;
            int pix = (3 * (l >> 5) + kh) * 96 + 3 * (l & 31) + kw;
            SK[li][c] = kfb[(size_t)pix * 64 + c];
            SQ[li][c] = qfb[(size_t)pix * 64 + c];
        }
        __syncthreads();
        #pragma unroll 8
        for (int li = 0; li < 32; li++) {
            float4 av = *reinterpret_cast<const float4*>(&SK[li][tc]);
            float4 bv = *reinterpret_cast<const float4*>(&SQ[li][td]);
            float a[4]  = {av.x, av.y, av.z, av.w};
            float bb[4] = {bv.x, bv.y, bv.z, bv.w};
            #pragma unroll
            for (int i = 0; i < 4; i++)
                #pragma unroll
                for (int j = 0; j < 4; j++)
                    acc[i][j] = fmaf(a[i], bb[j], acc[i][j]);
        }
    }
    const float sc = 1.0f / 24.0f;
    #pragma unroll
    for (int j = 0; j < 4; j++) {
        float* ap = g_sc[s] + ((size_t)(b * C + td + j)) * KK + k;
        #pragma unroll
        for (int i = 0; i < 4; i++)
            ap[(tc + i) * 9] = acc[i][j] * sc;
    }
}

// ---------------------------------------------------------------------------
// Reduce partials + softmax; write dyn weights w9d[b][k][d][c] (tf32).
// ---------------------------------------------------------------------------
__global__ void __launch_bounds__(256) softmax_kernel()
{
    const int row  = blockIdx.x * 8 + (threadIdx.x >> 5);   // b*64 + d
    const int lane = threadIdx.x & 31;
    const int b = row >> 6, d = row & 63;
    const size_t off = (size_t)row * KK;

    float v[18];
    float m = -3.4e38f;
    #pragma unroll
    for (int i = 0; i < 18; i++) {
        int idx = lane + i * 32;
        float t = 0.f;
        #pragma unroll
        for (int s = 0; s < NSLICE; s++) t += g_sc[s][off + idx];
        v[i] = t;
        m = fmaxf(m, t);
    }
    #pragma unroll
    for (int o = 16; o > 0; o >>= 1) m = fmaxf(m, __shfl_xor_sync(0xffffffffu, m, o));
    float ss = 0.f;
    #pragma unroll
    for (int i = 0; i < 18; i++) { v[i] = __expf(v[i] - m); ss += v[i]; }
    #pragma unroll
    for (int o = 16; o > 0; o >>= 1) ss += __shfl_xor_sync(0xffffffffu, ss, o);
    float inv = 1.0f / ss;
    #pragma unroll
    for (int i = 0; i < 18; i++) {
        int idx = lane + i * 32;           // idx = c*9 + k
        int c = idx / 9, k = idx - c * 9;
        g_w9d[(((size_t)b * 9 + k) * 64 + d) * 64 + c] = tf32r(v[i] * inv);
    }
}

extern "C" void kernel_launch(void* const* d_in, const int* in_sizes, int n_in,
                              void* d_out, int out_size)
{
    const float* x1 = (const float*)d_in[0];
    const float* x2 = (const float*)d_in[1];
    const float* w1 = (const float*)d_in[2];
    const float* w2 = (const float*)d_in[3];
    const float* w3 = (const float*)d_in[4];
    float* out = (float*)d_out;

    cudaFuncSetAttribute(conv_tc_kernel,
                         cudaFuncAttributeMaxDynamicSharedMemorySize, SMEM_DYN);

    prep_w9s_kernel<<<(3 * 9 * 4096 + 255) / 256, 256>>>(w1, w2, w3);
    conv_tc_kernel<<<dim3(12, 16, 3), 256, SMEM_DYN>>>(x1, x2, out, 0);
    scores_kernel<<<dim3(9, 16, NSLICE), 256>>>();
    softmax_kernel<<<128, 256>>>();
    conv_tc_kernel<<<dim3(12, 16, 1), 256, SMEM_DYN>>>(x1, x2, out, 1);
}

// round 11
// speedup vs baseline: 1.5399x; 1.3100x over previous
#include <cuda_runtime.h>
#include <cuda_fp16.h>
#include <cstdint>

#define NB   16
#define C    64
#define HWSZ 9216
#define CHW  589824
#define KK   576
#define NSLICE 8

// Scratch. kf/qf NHWC fp32 (for scores); vf stored as pre-swizzled fp16
// A-blocks: one 16KB block per (b, image row), row px+1 holds column px.
__device__ float g_kf[NB * CHW];
__device__ float g_qf[NB * CHW];
__device__ __align__(16) __half g_vfh[NB * 96 * 8192];
__device__ float g_sc[NSLICE][NB * C * KK];
__device__ float g_w9s[3 * 9 * 64 * 64];   // [z][k9][cout][cin] fp32
__device__ float g_w9d[NB * 9 * 64 * 64];  // [b][k9][cout][cin] fp32

// tcgen05 is arch-SPECIFIC: only emit in the sm_103a/sm_100a pass.
#if defined(__CUDA_ARCH_FEAT_SM103_ALL) || defined(__CUDA_ARCH_FEAT_SM100_ALL) \
    || (defined(__CUDA_ARCH_SPECIFIC__) && (__CUDA_ARCH_SPECIFIC__ >= 1000))
#define HAS_TCGEN05 1
#else
#define HAS_TCGEN05 0
#endif

#if HAS_TCGEN05
__device__ __forceinline__ uint32_t smem_u32(const void* p) {
    uint32_t a;
    asm("{ .reg .u64 t; cvta.to.shared.u64 t, %1; cvt.u32.u64 %0, t; }"
        : "=r"(a) : "l"(p));
    return a;
}
__device__ __forceinline__ uint32_t elect_one() {
    uint32_t pred;
    asm volatile("{\n\t.reg .pred p;\n\telect.sync _|p, 0xFFFFFFFF;\n\t"
                 "selp.b32 %0, 1, 0, p;\n\t}" : "=r"(pred));
    return pred;
}

#define MBARRIER_INIT(addr, cnt) \
    asm volatile("mbarrier.init.shared.b64 [%0], %1;" :: "r"(addr), "r"(cnt) : "memory")
#define MBARRIER_INVAL(addr) \
    asm volatile("mbarrier.inval.shared.b64 [%0];" :: "r"(addr) : "memory")
#define MBARRIER_WAIT_PARITY(addr, par) do {                                   \
    uint32_t _m = (addr), _p = (par), _d;                                      \
    asm volatile("{\n\t.reg .pred p;\n\t"                                      \
        "mbarrier.try_wait.parity.acquire.cta.shared::cta.b64 p, [%1], %2;\n\t"\
        "selp.b32 %0, 1, 0, p;\n\t}" : "=r"(_d) : "r"(_m), "r"(_p) : "memory");\
    if (!_d) {                                                                 \
        asm volatile("{\n\t.reg .pred P1;\n\tWL%=:\n\t"                        \
        "mbarrier.try_wait.parity.acquire.cta.shared::cta.b64 P1, [%0], %1, 0x989680;\n\t" \
        "@P1 bra.uni WD%=;\n\tbra.uni WL%=;\n\tWD%=:\n\t}"                     \
        :: "r"(_m), "r"(_p) : "memory");                                       \
    } } while (0)

#define TCGEN05_ALLOC(res, n) \
    asm volatile("tcgen05.alloc.cta_group::1.sync.aligned.shared::cta.b32 [%0], %1;" \
                 :: "r"(res), "r"((uint32_t)(n)) : "memory")
#define TCGEN05_DEALLOC(t, n) \
    asm volatile("tcgen05.dealloc.cta_group::1.sync.aligned.b32 %0, %1;" :: "r"(t), "r"((uint32_t)(n)))
#define TCGEN05_RELINQ() \
    asm volatile("tcgen05.relinquish_alloc_permit.cta_group::1.sync.aligned;")
#define TCGEN05_COMMIT(mb) \
    asm volatile("tcgen05.commit.cta_group::1.mbarrier::arrive::one.shared::cluster.b64 [%0];" \
                 :: "r"(mb) : "memory")
#define TCGEN05_FENCE_AFTER()  asm volatile("tcgen05.fence::after_thread_sync;" ::: "memory")
#define TCGEN05_FENCE_BEFORE() asm volatile("tcgen05.fence::before_thread_sync;" ::: "memory")
#define TCGEN05_WAIT_LD()      asm volatile("tcgen05.wait::ld.sync.aligned;" ::: "memory")
#define FENCE_ASYNC_SHARED()   asm volatile("fence.proxy.async.shared::cta;" ::: "memory")

#define TCGEN05_LD_X32(r, ta) \
    asm volatile("tcgen05.ld.sync.aligned.32x32b.x32.b32 "                     \
        "{%0,%1,%2,%3,%4,%5,%6,%7,%8,%9,%10,%11,%12,%13,%14,%15,"             \
        "%16,%17,%18,%19,%20,%21,%22,%23,%24,%25,%26,%27,%28,%29,%30,%31}, [%32];" \
        : "=r"((r)[0]),"=r"((r)[1]),"=r"((r)[2]),"=r"((r)[3]),                 \
          "=r"((r)[4]),"=r"((r)[5]),"=r"((r)[6]),"=r"((r)[7]),                 \
          "=r"((r)[8]),"=r"((r)[9]),"=r"((r)[10]),"=r"((r)[11]),               \
          "=r"((r)[12]),"=r"((r)[13]),"=r"((r)[14]),"=r"((r)[15]),             \
          "=r"((r)[16]),"=r"((r)[17]),"=r"((r)[18]),"=r"((r)[19]),             \
          "=r"((r)[20]),"=r"((r)[21]),"=r"((r)[22]),"=r"((r)[23]),             \
          "=r"((r)[24]),"=r"((r)[25]),"=r"((r)[26]),"=r"((r)[27]),             \
          "=r"((r)[28]),"=r"((r)[29]),"=r"((r)[30]),"=r"((r)[31])              \
        : "r"(ta))

__device__ __forceinline__ void mma_f16(uint32_t d, uint64_t a, uint64_t b,
                                        uint32_t idesc, uint32_t en) {
    asm volatile("{\n\t.reg .pred p;\n\tsetp.ne.u32 p, %5, 0;\n\t"
                 "tcgen05.mma.cta_group::1.kind::f16 [%0], %1, %2, %3, {%4,%4,%4,%4}, p;\n\t}"
                 :: "r"(d), "l"(a), "l"(b), "r"(idesc), "r"(0u), "r"(en) : "memory");
}

static __device__ __forceinline__ uint64_t mk_desc(uint32_t addr) {
    return ((uint64_t)2 << 61) | ((uint64_t)1 << 46) | ((uint64_t)64 << 32)
         | ((uint64_t)1 << 16) | (uint64_t)((addr >> 4) & 0x3FFF);
}
#endif  // HAS_TCGEN05

__device__ __forceinline__ uint32_t sw128(uint32_t off) { return off ^ ((off >> 3) & 0x70); }

// idesc kind::f16 (fp16 in, fp32 acc): dtype F32=1<<4, atype=btype=fp16=0,
// N=64 -> 8<<17, M=128 -> 8<<24
#define IDESC_F16 ((1u << 4) | (8u << 17) | (8u << 24))

#define NBUF       6
#define ABUF_BYTES 16384              // 128 rows * 128B (64 cin fp16 per row)
#define BTILE      8192               // 64 cout rows * 128B per shift
#define BREG_OFF   (NBUF * ABUF_BYTES)
#define SMEM_DYN   (1024 + BREG_OFF + 9 * BTILE)

__device__ __forceinline__ uint4 pack8h(const float* f) {
    __half2 h0 = __floats2half2_rn(f[0], f[1]);
    __half2 h1 = __floats2half2_rn(f[2], f[3]);
    __half2 h2 = __floats2half2_rn(f[4], f[5]);
    __half2 h3 = __floats2half2_rn(f[6], f[7]);
    uint4 u;
    u.x = *(uint32_t*)&h0; u.y = *(uint32_t*)&h1;
    u.z = *(uint32_t*)&h2; u.w = *(uint32_t*)&h3;
    return u;
}

// ---------------------------------------------------------------------------
// fp16 tensor-core conv. Grid (12, 16, z). 256 threads. 8 MMA passes, K=576.
// ---------------------------------------------------------------------------
__global__ void __launch_bounds__(256, 1)
conv_tc_kernel(const float* __restrict__ x1, const float* __restrict__ x2,
               float* __restrict__ out, int dyn)
{
#if HAS_TCGEN05
    extern __shared__ char smem[];
    __shared__ uint32_t s_tmem;
    __shared__ alignas(16) unsigned long long s_mbar[4];

    const int tid = threadIdx.x;
    const int wid = tid >> 5, lid = tid & 31;
    const int r0  = blockIdx.x * 8;
    const int b   = blockIdx.y;
    const int z   = blockIdx.z;

    uint32_t sm0 = smem_u32(smem);
    uint32_t Ab  = (sm0 + 1023) & ~1023u;
    uint32_t Bb  = Ab + BREG_OFF;
    char* Abp = smem + (Ab - sm0);
    char* Bbp = smem + (Bb - sm0);
    uint32_t mb[4] = { smem_u32(&s_mbar[0]), smem_u32(&s_mbar[1]),
                       smem_u32(&s_mbar[2]), smem_u32(&s_mbar[3]) };

    if (wid == 0) TCGEN05_ALLOC(smem_u32(&s_tmem), 512);
    if (tid < 4) MBARRIER_INIT(mb[tid], 1);
    // zero halo rows (row 0 = col -1; rows 97..127) of all ring buffers
    for (int i = tid; i < NBUF * 32 * 32; i += 256) {
        int buf = i >> 10, rr = i & 1023, row = rr >> 5, wd = rr & 31;
        int prow = (row == 0) ? 0 : (96 + row);
        *(float*)(Abp + buf * ABUF_BYTES + prow * 128 + wd * 4) = 0.f;
    }
    if (wid == 0) TCGEN05_RELINQ();
    __syncthreads();
    const uint32_t tmem = s_tmem;

    const float* xsrc = dyn ? nullptr : ((z == 1) ? x2 : x1);

    // ---- B: load once, fp32 gmem -> fp16 SW128 smem (9 x 64co x 64ci) ----
    {
        const float* wsrc = dyn ? (g_w9d + (size_t)b * 9 * 4096)
                                : (g_w9s + (size_t)z * 9 * 4096);
        #pragma unroll
        for (int it = 0; it < 18; it++) {
            int idx = it * 256 + tid;             // 0..4607
            int k9 = idx >> 9, r2 = idx & 511, co = r2 >> 3, ci8 = r2 & 7;
            float f[8];
            const float* p = wsrc + ((size_t)k9 * 64 + co) * 64 + ci8 * 8;
            *(float4*)(f)     = *(const float4*)(p);
            *(float4*)(f + 4) = *(const float4*)(p + 4);
            *(uint4*)(Bbp + k9 * BTILE + sw128(co * 128 + ci8 * 16)) = pack8h(f);
        }
    }

    // ---- A staging: uint4 v[3][2] per row-buffer ----
    auto issue_ldg = [&](uint4 (*v)[2], int ri) {
        bool valid = ((unsigned)ri < 96u);
        if (!dyn) {
            const float* src = xsrc + (size_t)b * CHW + (size_t)ri * 96;
            #pragma unroll
            for (int it = 0; it < 3; it++) {
                int idx = it * 256 + tid;
                int px = idx % 96, cg = idx / 96;      // cg: 8-cin group
                float f[8];
                #pragma unroll
                for (int j = 0; j < 8; j++)
                    f[j] = valid ? src[(size_t)(cg * 8 + j) * HWSZ + px] : 0.f;
                v[it][0] = *(uint4*)(f);
                v[it][1] = *(uint4*)(f + 4);
            }
        } else {
            const char* blk = (const char*)g_vfh + ((size_t)(b * 96 + ri) << 14);
            #pragma unroll
            for (int it = 0; it < 3; it++) {
                int idx = it * 256 + tid;
                v[it][0] = valid ? *(const uint4*)(blk + 128 + idx * 16)
                                 : make_uint4(0, 0, 0, 0);
            }
        }
    };
    auto store_a = [&](char* abuf, uint4 (*v)[2]) {
        if (!dyn) {
            #pragma unroll
            for (int it = 0; it < 3; it++) {
                int idx = it * 256 + tid;
                int px = idx % 96, cg = idx / 96;
                float f[8];
                *(uint4*)(f) = v[it][0];
                *(uint4*)(f + 4) = v[it][1];
                *(uint4*)(abuf + sw128((px + 1) * 128 + cg * 16)) = pack8h(f);
            }
        } else {
            #pragma unroll
            for (int it = 0; it < 3; it++) {
                int idx = it * 256 + tid;
                *(uint4*)(abuf + 128 + idx * 16) = v[it][0];  // pre-swizzled
            }
        }
    };

    // ---- prologue: rows r0-1 .. r0+2 ----
    uint4 v0[3][2], v1[3][2], v2[3][2], pf[3][2];
    issue_ldg(v0, r0 - 1);
    issue_ldg(v1, r0);
    issue_ldg(v2, r0 + 1);
    issue_ldg(pf, r0 + 2);
    store_a(Abp + 0 * ABUF_BYTES, v0);
    store_a(Abp + 1 * ABUF_BYTES, v1);
    store_a(Abp + 2 * ABUF_BYTES, v2);
    __syncthreads();
    FENCE_ASYNC_SHARED();

    for (int r = 0; r < 8; r++) {
        if (wid == 0 && elect_one()) {
            #pragma unroll
            for (int s = 0; s < 9; s++) {
                int kh = s / 3, kw = s - kh * 3;
                int buf = (r + kh) % NBUF;
                uint64_t ad = mk_desc(Ab + buf * ABUF_BYTES + kw * 128);
                uint64_t bd = mk_desc(Bb + s * BTILE);
                #pragma unroll
                for (int ks = 0; ks < 4; ks++)      // K=16 fp16 per step
                    mma_f16(tmem + r * 64, ad + ks * 2, bd + ks * 2,
                            IDESC_F16, (s | ks) != 0);
            }
            TCGEN05_COMMIT(mb[r & 3]);
        }
        if (r < 7) {
            if (r >= 3) {                   // buffer last read by pass r-3
                int k = r - 3;
                MBARRIER_WAIT_PARITY(mb[k & 3], 0);
            }
            store_a(Abp + ((r + 3) % NBUF) * ABUF_BYTES, pf);
            if (r < 6) issue_ldg(pf, r0 + r + 3);
            __syncthreads();
            FENCE_ASYNC_SHARED();
        }
    }
    MBARRIER_WAIT_PARITY(mb[3], 1);          // pass 7 (k=7: mb[3], parity 1)
    TCGEN05_FENCE_AFTER();

    // ---- epilogue: 6 warps; (wid&3)<3 active; half = wid>>2 ----
    if ((wid & 3) < 3) {
        int half = wid >> 2;
        int px   = (wid & 3) * 32 + lid;
        for (int r = 0; r < 8; r++) {
            uint32_t d0[32];
            TCGEN05_LD_X32(d0, tmem + r * 64 + half * 32);
            TCGEN05_WAIT_LD();
            if (!dyn) {
                if (z == 2) {
                    // vf: write pre-swizzled fp16 A-block for (b, r0+r)
                    float f[32];
                    #pragma unroll
                    for (int q = 0; q < 32; q++) f[q] = __uint_as_float(d0[q]);
                    char* blk = (char*)g_vfh + ((size_t)(b * 96 + r0 + r) << 14);
                    #pragma unroll
                    for (int j = 0; j < 4; j++)
                        *(uint4*)(blk + sw128((px + 1) * 128 + half * 64 + j * 16))
                            = pack8h(f + j * 8);
                } else {
                    float* dst = ((z == 0) ? g_kf : g_qf)
                               + ((size_t)b * HWSZ + (size_t)(r0 + r) * 96 + px) * 64
                               + half * 32;
                    #pragma unroll
                    for (int q = 0; q < 8; q++)
                        *(float4*)(dst + q * 4) = make_float4(
                            __uint_as_float(d0[q*4]),   __uint_as_float(d0[q*4+1]),
                            __uint_as_float(d0[q*4+2]), __uint_as_float(d0[q*4+3]));
                }
            } else {
                float* dst = out + (size_t)b * CHW + (size_t)(r0 + r) * 96 + px
                           + (size_t)half * 32 * HWSZ;
                #pragma unroll
                for (int c = 0; c < 32; c++)
                    dst[(size_t)c * HWSZ] = __uint_as_float(d0[c]);
            }
        }
    }
    TCGEN05_FENCE_BEFORE();
    __syncthreads();
    if (tid < 4) MBARRIER_INVAL(mb[tid]);
    __syncthreads();
    if (wid == 0) TCGEN05_DEALLOC(tmem, 512);
#endif  // HAS_TCGEN05
}

// ---------------------------------------------------------------------------
// Static-weight transpose: w9s[z][k][cout][cin] (fp32)
// ---------------------------------------------------------------------------
__global__ void __launch_bounds__(256) prep_w9s_kernel(
    const float* __restrict__ w1, const float* __restrict__ w2,
    const float* __restrict__ w3)
{
    int idx = blockIdx.x * 256 + threadIdx.x;
    if (idx >= 3 * 9 * 4096) return;
    int z = idx / 36864, rem = idx - z * 36864;
    int k = rem >> 12, r2 = rem & 4095, co = r2 >> 6, ci = r2 & 63;
    const float* w = (z == 0) ? w1 : (z == 1) ? w2 : w3;
    g_w9s[idx] = w[co * 576 + ci * 9 + k];
}

// ---------------------------------------------------------------------------
// scores partials (NHWC). Grid (9, 16, NSLICE), block 256. 128 L per slice.
// ---------------------------------------------------------------------------
__global__ void __launch_bounds__(256) scores_kernel()
{
    const int k  = blockIdx.x, b = blockIdx.y, s = blockIdx.z;
    const int kh = k / 3, kw = k % 3;
    const float* kfb = g_kf + (size_t)b * CHW;
    const float* qfb = g_qf + (size_t)b * CHW;

    __shared__ float SK[32][68];
    __shared__ float SQ[32][68];

    const int tid = threadIdx.x;
    const int tc  = (tid & 15) << 2;
    const int td  = (tid >> 4) << 2;

    float acc[4][4] = {};
    for (int l0 = s * 128; l0 < s * 128 + 128; l0 += 32) {
        __syncthreads();
        #pragma unroll
        for (int it = 0; it < 8; it++) {
            int idx = tid + it * 256;           // 0..2047
            int li = idx >> 6, c = idx & 63;
            int l = l0 + li;
            int pix = (3 * (l >> 5) + kh) * 96 + 3 * (l & 31) + kw;
            SK[li][c] = kfb[(size_t)pix * 64 + c];
            SQ[li][c] = qfb[(size_t)pix * 64 + c];
        }
        __syncthreads();
        #pragma unroll 8
        for (int li = 0; li < 32; li++) {
            float4 av = *reinterpret_cast<const float4*>(&SK[li][tc]);
            float4 bv = *reinterpret_cast<const float4*>(&SQ[li][td]);
            float a[4]  = {av.x, av.y, av.z, av.w};
            float bb[4] = {bv.x, bv.y, bv.z, bv.w};
            #pragma unroll
            for (int i = 0; i < 4; i++)
                #pragma unroll
                for (int j = 0; j < 4; j++)
                    acc[i][j] = fmaf(a[i], bb[j], acc[i][j]);
        }
    }
    const float sc = 1.0f / 24.0f;
    #pragma unroll
    for (int j = 0; j < 4; j++) {
        float* ap = g_sc[s] + ((size_t)(b * C + td + j)) * KK + k;
        #pragma unroll
        for (int i = 0; i < 4; i++)
            ap[(tc + i) * 9] = acc[i][j] * sc;
    }
}

// ---------------------------------------------------------------------------
// Reduce partials + softmax; write dyn weights w9d[b][k][d][c] (fp32).
// Grid 256, block 128 (4 rows/block).
// ---------------------------------------------------------------------------
__global__ void __launch_bounds__(128) softmax_kernel()
{
    const int row  = blockIdx.x * 4 + (threadIdx.x >> 5);   // b*64 + d
    const int lane = threadIdx.x & 31;
    const int b = row >> 6, d = row & 63;
    const size_t off = (size_t)row * KK;

    float v[18];
    float m = -3.4e38f;
    #pragma unroll
    for (int i = 0; i < 18; i++) {
        int idx = lane + i * 32;
        float t = 0.f;
        #pragma unroll
        for (int s = 0; s < NSLICE; s++) t += g_sc[s][off + idx];
        v[i] = t;
        m = fmaxf(m, t);
    }
    #pragma unroll
    for (int o = 16; o > 0; o >>= 1) m = fmaxf(m, __shfl_xor_sync(0xffffffffu, m, o));
    float ss = 0.f;
    #pragma unroll
    for (int i = 0; i < 18; i++) { v[i] = __expf(v[i] - m); ss += v[i]; }
    #pragma unroll
    for (int o = 16; o > 0; o >>= 1) ss += __shfl_xor_sync(0xffffffffu, ss, o);
    float inv = 1.0f / ss;
    #pragma unroll
    for (int i = 0; i < 18; i++) {
        int idx = lane + i * 32;           // idx = c*9 + k
        int c = idx / 9, k = idx - c * 9;
        g_w9d[(((size_t)b * 9 + k) * 64 + d) * 64 + c] = v[i] * inv;
    }
}

extern "C" void kernel_launch(void* const* d_in, const int* in_sizes, int n_in,
                              void* d_out, int out_size)
{
    const float* x1 = (const float*)d_in[0];
    const float* x2 = (const float*)d_in[1];
    const float* w1 = (const float*)d_in[2];
    const float* w2 = (const float*)d_in[3];
    const float* w3 = (const float*)d_in[4];
    float* out = (float*)d_out;

    cudaFuncSetAttribute(conv_tc_kernel,
                         cudaFuncAttributeMaxDynamicSharedMemorySize, SMEM_DYN);

    prep_w9s_kernel<<<(3 * 9 * 4096 + 255) / 256, 256>>>(w1, w2, w3);
    conv_tc_kernel<<<dim3(12, 16, 3), 256, SMEM_DYN>>>(x1, x2, out, 0);
    scores_kernel<<<dim3(9, 16, NSLICE), 256>>>();
    softmax_kernel<<<256, 128>>>();
    conv_tc_kernel<<<dim3(12, 16, 1), 256, SMEM_DYN>>>(x1, x2, out, 1);
}